// round 1
// baseline (speedup 1.0000x reference)
#include <cuda_runtime.h>
#include <cuda_bf16.h>

// Problem constants
#define D_MODEL 2048
#define N_HEADS 16
#define HEAD_DIM 128
#define BATCH 2
#define SEQ_T 1024
#define XL_LEN 1024
#define KV_LEN (SEQ_T + XL_LEN)   // 2048
#define M_ROWS (BATCH * SEQ_T)    // 2048

// Scratch (device globals; no allocation allowed)
__device__ float g_qkv[M_ROWS * 3 * D_MODEL];                       // 50 MB
__device__ float g_Q[BATCH * N_HEADS * SEQ_T * HEAD_DIM];           // 16 MB
__device__ float g_K[BATCH * N_HEADS * KV_LEN * HEAD_DIM];          // 32 MB
__device__ float g_V[BATCH * N_HEADS * KV_LEN * HEAD_DIM];          // 32 MB
__device__ float g_Y[M_ROWS * D_MODEL];                             // 16 MB

// ---------------------------------------------------------------------------
// SGEMM (NT): C[M,N] = A[M,K] @ B[N,K]^T, all row-major.
// 128x128 block tile, BK=8, 8x8 per-thread tile, 256 threads, prefetch.
// ---------------------------------------------------------------------------
__global__ __launch_bounds__(256, 2)
void sgemm_nt(const float* __restrict__ A, const float* __restrict__ B,
              float* __restrict__ C, int M, int N, int K) {
    __shared__ float As[8][132];
    __shared__ float Bs[8][132];

    const int tid = threadIdx.x;
    const int bm = blockIdx.y * 128;
    const int bn = blockIdx.x * 128;

    const int lr = tid >> 1;          // 0..127 (tile row to load)
    const int lc = (tid & 1) * 4;     // 0 or 4 (k offset)
    const int tx = tid & 15;          // 0..15
    const int ty = tid >> 4;          // 0..15

    const float* Ap = A + (size_t)(bm + lr) * K + lc;
    const float* Bp = B + (size_t)(bn + lr) * K + lc;

    float acc[8][8];
#pragma unroll
    for (int i = 0; i < 8; i++)
#pragma unroll
        for (int j = 0; j < 8; j++) acc[i][j] = 0.f;

    float4 av = *(const float4*)(Ap);
    float4 bv = *(const float4*)(Bp);

    for (int k0 = 0; k0 < K; k0 += 8) {
        As[lc + 0][lr] = av.x; As[lc + 1][lr] = av.y;
        As[lc + 2][lr] = av.z; As[lc + 3][lr] = av.w;
        Bs[lc + 0][lr] = bv.x; Bs[lc + 1][lr] = bv.y;
        Bs[lc + 2][lr] = bv.z; Bs[lc + 3][lr] = bv.w;
        __syncthreads();

        if (k0 + 8 < K) {
            av = *(const float4*)(Ap + k0 + 8);
            bv = *(const float4*)(Bp + k0 + 8);
        }

#pragma unroll
        for (int kk = 0; kk < 8; kk++) {
            float4 a0 = *(const float4*)&As[kk][ty * 8];
            float4 a1 = *(const float4*)&As[kk][ty * 8 + 4];
            float4 b0 = *(const float4*)&Bs[kk][tx * 8];
            float4 b1 = *(const float4*)&Bs[kk][tx * 8 + 4];
            float ar[8] = {a0.x, a0.y, a0.z, a0.w, a1.x, a1.y, a1.z, a1.w};
            float br[8] = {b0.x, b0.y, b0.z, b0.w, b1.x, b1.y, b1.z, b1.w};
#pragma unroll
            for (int i = 0; i < 8; i++)
#pragma unroll
                for (int j = 0; j < 8; j++)
                    acc[i][j] += ar[i] * br[j];
        }
        __syncthreads();
    }

#pragma unroll
    for (int i = 0; i < 8; i++) {
        int row = bm + ty * 8 + i;
        float* crow = C + (size_t)row * N + bn + tx * 8;
        *(float4*)(crow)     = make_float4(acc[i][0], acc[i][1], acc[i][2], acc[i][3]);
        *(float4*)(crow + 4) = make_float4(acc[i][4], acc[i][5], acc[i][6], acc[i][7]);
    }
}

// ---------------------------------------------------------------------------
// Prep: RoPE(q) -> g_Q[b][h][t][d]; RoPE(k_cur) -> g_K[b][h][XL+t][d];
//       k_xl + pos_emb -> g_K[b][h][t][d]; v_cur/v_xl -> g_V.
// One thread per (b,t,h,pair). 2M threads.
// ---------------------------------------------------------------------------
__global__ void prep_kernel(const float* __restrict__ k_xl,
                            const float* __restrict__ v_xl,
                            const float* __restrict__ pos_emb,
                            const float* __restrict__ cosb,
                            const float* __restrict__ sinb) {
    int idx = blockIdx.x * blockDim.x + threadIdx.x;
    // idx = ((b*T + t)*H + h)*64 + i
    int i = idx & 63;
    int h = (idx >> 6) & (N_HEADS - 1);
    int t = (idx >> 10) & (SEQ_T - 1);
    int b = idx >> 20;
    if (b >= BATCH) return;

    int m = b * SEQ_T + t;
    float c = cosb[t * 64 + i];
    float s = sinb[t * 64 + i];
    int d0 = 2 * i;

    const float* qk_row = g_qkv + (size_t)m * (3 * D_MODEL);

    // q with rope
    {
        float2 xv = *(const float2*)(qk_row + h * HEAD_DIM + d0);
        float2 o;
        o.x = xv.x * c - xv.y * s;
        o.y = xv.x * s + xv.y * c;
        int base = ((b * N_HEADS + h) * SEQ_T + t) * HEAD_DIM + d0;
        *(float2*)(g_Q + base) = o;
    }
    // k current with rope -> kv index XL_LEN + t
    {
        float2 xv = *(const float2*)(qk_row + D_MODEL + h * HEAD_DIM + d0);
        float2 o;
        o.x = xv.x * c - xv.y * s;
        o.y = xv.x * s + xv.y * c;
        int base = ((b * N_HEADS + h) * KV_LEN + XL_LEN + t) * HEAD_DIM + d0;
        *(float2*)(g_K + base) = o;
    }
    // v current
    {
        float2 xv = *(const float2*)(qk_row + 2 * D_MODEL + h * HEAD_DIM + d0);
        int base = ((b * N_HEADS + h) * KV_LEN + XL_LEN + t) * HEAD_DIM + d0;
        *(float2*)(g_V + base) = xv;
    }
    // k_xl + pos_emb, v_xl -> kv index t
    {
        int src = (b * XL_LEN + t) * D_MODEL + h * HEAD_DIM + d0;
        int psrc = t * D_MODEL + h * HEAD_DIM + d0;
        float2 kv = *(const float2*)(k_xl + src);
        float2 pv = *(const float2*)(pos_emb + psrc);
        float2 vv = *(const float2*)(v_xl + src);
        float2 ko; ko.x = kv.x + pv.x; ko.y = kv.y + pv.y;
        int base = ((b * N_HEADS + h) * KV_LEN + t) * HEAD_DIM + d0;
        *(float2*)(g_K + base) = ko;
        *(float2*)(g_V + base) = vv;
    }
}

// ---------------------------------------------------------------------------
// Flash attention, fp32. Block = 256 threads handles a 64-row Q tile for one
// (b,h). Streams KV in 64-row chunks with online softmax.
// ---------------------------------------------------------------------------
__global__ __launch_bounds__(256, 1)
void attn_kernel(const int* __restrict__ iscp) {
    __shared__ float Qs[64][132];
    __shared__ float Ks[64][132];
    __shared__ float Vs[64][128];
    __shared__ float Ss[64][65];
    __shared__ float m_s[64], l_s[64], c_s[64];

    const int tid = threadIdx.x;
    const int q0 = blockIdx.x * 64;
    const int h = blockIdx.y;
    const int b = blockIdx.z;
    const bool causal = (*iscp) != 0;
    const float scale = 0.08838834764831845f;  // 1/sqrt(128)

    const float* Qg = g_Q + (size_t)(b * N_HEADS + h) * SEQ_T * HEAD_DIM;
    const float* Kg = g_K + (size_t)(b * N_HEADS + h) * KV_LEN * HEAD_DIM;
    const float* Vg = g_V + (size_t)(b * N_HEADS + h) * KV_LEN * HEAD_DIM;

    // load Q tile (64 x 128)
#pragma unroll
    for (int it = 0; it < 8; it++) {
        int idx = tid + it * 256;
        int r = idx >> 5;
        int f4 = (idx & 31) * 4;
        *(float4*)&Qs[r][f4] = *(const float4*)(Qg + (size_t)(q0 + r) * HEAD_DIM + f4);
    }
    if (tid < 64) { m_s[tid] = -1e30f; l_s[tid] = 0.f; }

    const int r0 = (tid >> 3) * 2;       // O rows (2 per thread)
    const int d0 = (tid & 7) * 16;       // O d-slice
    const int ty = tid >> 4;             // S compute: 16x16 thread grid
    const int tx = tid & 15;

    float O0[16], O1[16];
#pragma unroll
    for (int d = 0; d < 16; d++) { O0[d] = 0.f; O1[d] = 0.f; }

    __syncthreads();

    for (int kc = 0; kc < KV_LEN; kc += 64) {
        // load K,V chunk
#pragma unroll
        for (int it = 0; it < 8; it++) {
            int idx = tid + it * 256;
            int r = idx >> 5;
            int f4 = (idx & 31) * 4;
            *(float4*)&Ks[r][f4] = *(const float4*)(Kg + (size_t)(kc + r) * HEAD_DIM + f4);
            *(float4*)&Vs[r][f4] = *(const float4*)(Vg + (size_t)(kc + r) * HEAD_DIM + f4);
        }
        __syncthreads();

        // S = Qs @ Ks^T : 4x4 micro-tile
        float sacc[4][4];
#pragma unroll
        for (int i = 0; i < 4; i++)
#pragma unroll
            for (int j = 0; j < 4; j++) sacc[i][j] = 0.f;

#pragma unroll
        for (int dd = 0; dd < HEAD_DIM; dd += 4) {
            float4 a[4], bb[4];
#pragma unroll
            for (int i = 0; i < 4; i++) a[i] = *(const float4*)&Qs[ty * 4 + i][dd];
#pragma unroll
            for (int j = 0; j < 4; j++) bb[j] = *(const float4*)&Ks[tx * 4 + j][dd];
#pragma unroll
            for (int i = 0; i < 4; i++)
#pragma unroll
                for (int j = 0; j < 4; j++) {
                    sacc[i][j] += a[i].x * bb[j].x;
                    sacc[i][j] += a[i].y * bb[j].y;
                    sacc[i][j] += a[i].z * bb[j].z;
                    sacc[i][j] += a[i].w * bb[j].w;
                }
        }

#pragma unroll
        for (int i = 0; i < 4; i++)
#pragma unroll
            for (int j = 0; j < 4; j++) {
                float sv = sacc[i][j] * scale;
                if (causal && (kc + tx * 4 + j) > (q0 + ty * 4 + i) + (KV_LEN - SEQ_T))
                    sv = -1e30f;
                Ss[ty * 4 + i][tx * 4 + j] = sv;
            }
        __syncthreads();

        // online softmax: 4 lanes per row, 16 cols each
        {
            int row = tid >> 2;
            int part = tid & 3;
            float vals[16];
            float mx = -1e30f;
#pragma unroll
            for (int u = 0; u < 16; u++) {
                vals[u] = Ss[row][part * 16 + u];
                mx = fmaxf(mx, vals[u]);
            }
            mx = fmaxf(mx, __shfl_xor_sync(0xffffffffu, mx, 1));
            mx = fmaxf(mx, __shfl_xor_sync(0xffffffffu, mx, 2));
            float m_old = m_s[row];
            float m_new = fmaxf(m_old, mx);
            float sum = 0.f;
#pragma unroll
            for (int u = 0; u < 16; u++) {
                float p = __expf(vals[u] - m_new);
                Ss[row][part * 16 + u] = p;
                sum += p;
            }
            sum += __shfl_xor_sync(0xffffffffu, sum, 1);
            sum += __shfl_xor_sync(0xffffffffu, sum, 2);
            if (part == 0) {
                float cf = __expf(m_old - m_new);
                l_s[row] = l_s[row] * cf + sum;
                m_s[row] = m_new;
                c_s[row] = cf;
            }
        }
        __syncthreads();

        // O = O * c + P @ V  (2 rows x 16 d per thread)
        {
            float cf0 = c_s[r0];
            float cf1 = c_s[r0 + 1];
#pragma unroll
            for (int d = 0; d < 16; d++) { O0[d] *= cf0; O1[d] *= cf1; }
#pragma unroll 4
            for (int j = 0; j < 64; j++) {
                float p0 = Ss[r0][j];
                float p1 = Ss[r0 + 1][j];
#pragma unroll
                for (int d4 = 0; d4 < 16; d4 += 4) {
                    float4 v = *(const float4*)&Vs[j][d0 + d4];
                    O0[d4 + 0] += p0 * v.x; O0[d4 + 1] += p0 * v.y;
                    O0[d4 + 2] += p0 * v.z; O0[d4 + 3] += p0 * v.w;
                    O1[d4 + 0] += p1 * v.x; O1[d4 + 1] += p1 * v.y;
                    O1[d4 + 2] += p1 * v.z; O1[d4 + 3] += p1 * v.w;
                }
            }
        }
        __syncthreads();
    }

    // finalize: Y[b][t][h*128+d] = O / l
    float inv0 = 1.f / l_s[r0];
    float inv1 = 1.f / l_s[r0 + 1];
    float* y0 = g_Y + (size_t)(b * SEQ_T + q0 + r0) * D_MODEL + h * HEAD_DIM + d0;
    float* y1 = g_Y + (size_t)(b * SEQ_T + q0 + r0 + 1) * D_MODEL + h * HEAD_DIM + d0;
#pragma unroll
    for (int d4 = 0; d4 < 16; d4 += 4) {
        *(float4*)(y0 + d4) = make_float4(O0[d4] * inv0, O0[d4 + 1] * inv0,
                                          O0[d4 + 2] * inv0, O0[d4 + 3] * inv0);
        *(float4*)(y1 + d4) = make_float4(O1[d4] * inv1, O1[d4 + 1] * inv1,
                                          O1[d4 + 2] * inv1, O1[d4 + 3] * inv1);
    }
}

// ---------------------------------------------------------------------------
extern "C" void kernel_launch(void* const* d_in, const int* in_sizes, int n_in,
                              void* d_out, int out_size) {
    const float* x       = (const float*)d_in[0];
    const float* cosb    = (const float*)d_in[1];
    const float* sinb    = (const float*)d_in[2];
    const float* k_xl    = (const float*)d_in[3];
    const float* v_xl    = (const float*)d_in[4];
    const float* pos_emb = (const float*)d_in[5];
    const float* w_qkv   = (const float*)d_in[6];
    const float* w_proj  = (const float*)d_in[7];
    const int*   iscp    = (const int*)d_in[8];
    float* out = (float*)d_out;

    float *qkv_p = nullptr, *y_p = nullptr;
    cudaGetSymbolAddress((void**)&qkv_p, g_qkv);
    cudaGetSymbolAddress((void**)&y_p, g_Y);

    // 1) qkv = x @ w_qkv^T   [2048 x 6144 x 2048]
    sgemm_nt<<<dim3(3 * D_MODEL / 128, M_ROWS / 128), 256>>>(
        x, w_qkv, qkv_p, M_ROWS, 3 * D_MODEL, D_MODEL);

    // 2) rope / concat / layout
    {
        int total = BATCH * SEQ_T * N_HEADS * (HEAD_DIM / 2);
        prep_kernel<<<total / 256, 256>>>(k_xl, v_xl, pos_emb, cosb, sinb);
    }

    // 3) attention
    attn_kernel<<<dim3(SEQ_T / 64, N_HEADS, BATCH), 256>>>(iscp);

    // 4) out = y @ w_proj^T  [2048 x 2048 x 2048]
    sgemm_nt<<<dim3(D_MODEL / 128, M_ROWS / 128), 256>>>(
        y_p, w_proj, out, M_ROWS, D_MODEL, D_MODEL);
}

// round 3
// speedup vs baseline: 1.5129x; 1.5129x over previous
#include <cuda_runtime.h>
#include <cuda_bf16.h>

// Problem constants
#define D_MODEL 2048
#define N_HEADS 16
#define HEAD_DIM 128
#define BATCH 2
#define SEQ_T 1024
#define XL_LEN 1024
#define KV_LEN (SEQ_T + XL_LEN)   // 2048
#define M_ROWS (BATCH * SEQ_T)    // 2048

// Scratch (device globals; no allocation allowed)
__device__ float g_qkv[M_ROWS * 3 * D_MODEL];
__device__ float g_Q[BATCH * N_HEADS * SEQ_T * HEAD_DIM];
__device__ float g_K[BATCH * N_HEADS * KV_LEN * HEAD_DIM];
__device__ float g_V[BATCH * N_HEADS * KV_LEN * HEAD_DIM];
__device__ float g_Y[M_ROWS * D_MODEL];

// ---------------------------------------------------------------------------
// SGEMM (NT): C[M,N] = A[M,K] @ B[N,K]^T, all row-major.  (at FFMA rt=2 ceiling)
// ---------------------------------------------------------------------------
__global__ __launch_bounds__(256, 2)
void sgemm_nt(const float* __restrict__ A, const float* __restrict__ B,
              float* __restrict__ C, int M, int N, int K) {
    __shared__ float As[8][132];
    __shared__ float Bs[8][132];

    const int tid = threadIdx.x;
    const int bm = blockIdx.y * 128;
    const int bn = blockIdx.x * 128;

    const int lr = tid >> 1;
    const int lc = (tid & 1) * 4;
    const int tx = tid & 15;
    const int ty = tid >> 4;

    const float* Ap = A + (size_t)(bm + lr) * K + lc;
    const float* Bp = B + (size_t)(bn + lr) * K + lc;

    float acc[8][8];
#pragma unroll
    for (int i = 0; i < 8; i++)
#pragma unroll
        for (int j = 0; j < 8; j++) acc[i][j] = 0.f;

    float4 av = *(const float4*)(Ap);
    float4 bv = *(const float4*)(Bp);

    for (int k0 = 0; k0 < K; k0 += 8) {
        As[lc + 0][lr] = av.x; As[lc + 1][lr] = av.y;
        As[lc + 2][lr] = av.z; As[lc + 3][lr] = av.w;
        Bs[lc + 0][lr] = bv.x; Bs[lc + 1][lr] = bv.y;
        Bs[lc + 2][lr] = bv.z; Bs[lc + 3][lr] = bv.w;
        __syncthreads();

        if (k0 + 8 < K) {
            av = *(const float4*)(Ap + k0 + 8);
            bv = *(const float4*)(Bp + k0 + 8);
        }

#pragma unroll
        for (int kk = 0; kk < 8; kk++) {
            float4 a0 = *(const float4*)&As[kk][ty * 8];
            float4 a1 = *(const float4*)&As[kk][ty * 8 + 4];
            float4 b0 = *(const float4*)&Bs[kk][tx * 8];
            float4 b1 = *(const float4*)&Bs[kk][tx * 8 + 4];
            float ar[8] = {a0.x, a0.y, a0.z, a0.w, a1.x, a1.y, a1.z, a1.w};
            float br[8] = {b0.x, b0.y, b0.z, b0.w, b1.x, b1.y, b1.z, b1.w};
#pragma unroll
            for (int i = 0; i < 8; i++)
#pragma unroll
                for (int j = 0; j < 8; j++)
                    acc[i][j] += ar[i] * br[j];
        }
        __syncthreads();
    }

#pragma unroll
    for (int i = 0; i < 8; i++) {
        int row = bm + ty * 8 + i;
        float* crow = C + (size_t)row * N + bn + tx * 8;
        *(float4*)(crow)     = make_float4(acc[i][0], acc[i][1], acc[i][2], acc[i][3]);
        *(float4*)(crow + 4) = make_float4(acc[i][4], acc[i][5], acc[i][6], acc[i][7]);
    }
}

// ---------------------------------------------------------------------------
// Prep: RoPE(q) -> g_Q; RoPE(k_cur) -> g_K[.., XL+t]; k_xl+pos -> g_K[.., t];
//       v -> g_V.
// ---------------------------------------------------------------------------
__global__ void prep_kernel(const float* __restrict__ k_xl,
                            const float* __restrict__ v_xl,
                            const float* __restrict__ pos_emb,
                            const float* __restrict__ cosb,
                            const float* __restrict__ sinb) {
    int idx = blockIdx.x * blockDim.x + threadIdx.x;
    int i = idx & 63;
    int h = (idx >> 6) & (N_HEADS - 1);
    int t = (idx >> 10) & (SEQ_T - 1);
    int b = idx >> 20;
    if (b >= BATCH) return;

    int m = b * SEQ_T + t;
    float c = cosb[t * 64 + i];
    float s = sinb[t * 64 + i];
    int d0 = 2 * i;

    const float* qk_row = g_qkv + (size_t)m * (3 * D_MODEL);

    {
        float2 xv = *(const float2*)(qk_row + h * HEAD_DIM + d0);
        float2 o;
        o.x = xv.x * c - xv.y * s;
        o.y = xv.x * s + xv.y * c;
        int base = ((b * N_HEADS + h) * SEQ_T + t) * HEAD_DIM + d0;
        *(float2*)(g_Q + base) = o;
    }
    {
        float2 xv = *(const float2*)(qk_row + D_MODEL + h * HEAD_DIM + d0);
        float2 o;
        o.x = xv.x * c - xv.y * s;
        o.y = xv.x * s + xv.y * c;
        int base = ((b * N_HEADS + h) * KV_LEN + XL_LEN + t) * HEAD_DIM + d0;
        *(float2*)(g_K + base) = o;
    }
    {
        float2 xv = *(const float2*)(qk_row + 2 * D_MODEL + h * HEAD_DIM + d0);
        int base = ((b * N_HEADS + h) * KV_LEN + XL_LEN + t) * HEAD_DIM + d0;
        *(float2*)(g_V + base) = xv;
    }
    {
        int src = (b * XL_LEN + t) * D_MODEL + h * HEAD_DIM + d0;
        int psrc = t * D_MODEL + h * HEAD_DIM + d0;
        float2 kv = *(const float2*)(k_xl + src);
        float2 pv = *(const float2*)(pos_emb + psrc);
        float2 vv = *(const float2*)(v_xl + src);
        float2 ko; ko.x = kv.x + pv.x; ko.y = kv.y + pv.y;
        int base = ((b * N_HEADS + h) * KV_LEN + t) * HEAD_DIM + d0;
        *(float2*)(g_K + base) = ko;
        *(float2*)(g_V + base) = vv;
    }
}

// ---------------------------------------------------------------------------
// Flash attention, fp32. 128-row Q tile per block, 256 threads, 64-row KV
// chunks. S + online softmax fused in registers (shfl row reductions); only
// P round-trips through smem. 3 barriers per chunk.
// ---------------------------------------------------------------------------
#define SS_LD 68
constexpr int ATTN_SMEM_FLOATS =
    128 * 132 +   // Qs
    64 * 132 +    // Ks
    64 * 128 +    // Vs
    128 * SS_LD + // Ss (P)
    3 * 128;      // m, l, c
constexpr int ATTN_SMEM_BYTES = ATTN_SMEM_FLOATS * 4;

__global__ __launch_bounds__(256, 1)
void attn_kernel(const int* __restrict__ iscp) {
    extern __shared__ float sm[];
    float* Qs  = sm;                    // [128][132]
    float* Ks  = Qs + 128 * 132;        // [64][132]
    float* Vs  = Ks + 64 * 132;         // [64][128]
    float* Ss  = Vs + 64 * 128;         // [128][SS_LD]
    float* m_s = Ss + 128 * SS_LD;
    float* l_s = m_s + 128;
    float* c_s = l_s + 128;

    const int tid = threadIdx.x;
    const int q0 = blockIdx.x * 128;
    const int h = blockIdx.y;
    const int b = blockIdx.z;
    const bool causal = (*iscp) != 0;
    const float scale = 0.08838834764831845f;  // 1/sqrt(128)
    const int diag = KV_LEN - SEQ_T;

    const float* Qg = g_Q + (size_t)(b * N_HEADS + h) * SEQ_T * HEAD_DIM;
    const float* Kg = g_K + (size_t)(b * N_HEADS + h) * KV_LEN * HEAD_DIM;
    const float* Vg = g_V + (size_t)(b * N_HEADS + h) * KV_LEN * HEAD_DIM;

    // load Q tile (128 x 128), scale folded in
#pragma unroll
    for (int it = 0; it < 16; it++) {
        int idx = tid + it * 256;
        int r = idx >> 5;
        int c4 = (idx & 31) * 4;
        float4 q = *(const float4*)(Qg + (size_t)(q0 + r) * HEAD_DIM + c4);
        q.x *= scale; q.y *= scale; q.z *= scale; q.w *= scale;
        *(float4*)&Qs[r * 132 + c4] = q;
    }
    if (tid < 128) { m_s[tid] = -1e30f; l_s[tid] = 0.f; }

    const int ty = tid >> 4;          // 0..15 : owns rows ty*8..ty*8+7
    const int tx = tid & 15;          // 0..15 : owns cols tx*4..tx*4+3
    const int rr = (tid >> 3) * 4;    // PV: 4 rows
    const int dv = (tid & 7) * 16;    // PV: 16-wide d slice

    float O[4][16];
#pragma unroll
    for (int i = 0; i < 4; i++)
#pragma unroll
        for (int d = 0; d < 16; d++) O[i][d] = 0.f;

    __syncthreads();

    for (int kc = 0; kc < KV_LEN; kc += 64) {
        // ---- load K,V chunk (64 x 128 each) ----
#pragma unroll
        for (int it = 0; it < 8; it++) {
            int idx = tid + it * 256;
            int r = idx >> 5;
            int c4 = (idx & 31) * 4;
            *(float4*)&Ks[r * 132 + c4] =
                *(const float4*)(Kg + (size_t)(kc + r) * HEAD_DIM + c4);
            *(float4*)&Vs[r * 128 + c4] =
                *(const float4*)(Vg + (size_t)(kc + r) * HEAD_DIM + c4);
        }
        __syncthreads();

        // ---- S = Qs @ Ks^T (8x4 per thread), softmax fused ----
        float sacc[8][4];
#pragma unroll
        for (int i = 0; i < 8; i++)
#pragma unroll
            for (int j = 0; j < 4; j++) sacc[i][j] = 0.f;

#pragma unroll 2
        for (int dd = 0; dd < HEAD_DIM; dd += 4) {
            float4 bb[4];
#pragma unroll
            for (int j = 0; j < 4; j++)
                bb[j] = *(const float4*)&Ks[(tx * 4 + j) * 132 + dd];
#pragma unroll
            for (int i = 0; i < 8; i++) {
                float4 a = *(const float4*)&Qs[(ty * 8 + i) * 132 + dd];
#pragma unroll
                for (int j = 0; j < 4; j++) {
                    sacc[i][j] += a.x * bb[j].x;
                    sacc[i][j] += a.y * bb[j].y;
                    sacc[i][j] += a.z * bb[j].z;
                    sacc[i][j] += a.w * bb[j].w;
                }
            }
        }

        if (causal) {
#pragma unroll
            for (int i = 0; i < 8; i++)
#pragma unroll
                for (int j = 0; j < 4; j++)
                    if ((kc + tx * 4 + j) > (q0 + ty * 8 + i) + diag)
                        sacc[i][j] = -1e30f;
        }

        // per-row softmax: reduce across the 16 tx lanes (shfl within half-warp)
#pragma unroll
        for (int i = 0; i < 8; i++) {
            int row = ty * 8 + i;
            float mx = fmaxf(fmaxf(sacc[i][0], sacc[i][1]),
                             fmaxf(sacc[i][2], sacc[i][3]));
            mx = fmaxf(mx, __shfl_xor_sync(0xffffffffu, mx, 1));
            mx = fmaxf(mx, __shfl_xor_sync(0xffffffffu, mx, 2));
            mx = fmaxf(mx, __shfl_xor_sync(0xffffffffu, mx, 4));
            mx = fmaxf(mx, __shfl_xor_sync(0xffffffffu, mx, 8));
            float m_old = m_s[row];
            float m_new = fmaxf(m_old, mx);
            float4 p;
            p.x = __expf(sacc[i][0] - m_new);
            p.y = __expf(sacc[i][1] - m_new);
            p.z = __expf(sacc[i][2] - m_new);
            p.w = __expf(sacc[i][3] - m_new);
            float sum = (p.x + p.y) + (p.z + p.w);
            sum += __shfl_xor_sync(0xffffffffu, sum, 1);
            sum += __shfl_xor_sync(0xffffffffu, sum, 2);
            sum += __shfl_xor_sync(0xffffffffu, sum, 4);
            sum += __shfl_xor_sync(0xffffffffu, sum, 8);
            *(float4*)&Ss[row * SS_LD + tx * 4] = p;
            if (tx == 0) {
                float cf = __expf(m_old - m_new);
                l_s[row] = l_s[row] * cf + sum;
                m_s[row] = m_new;
                c_s[row] = cf;
            }
        }
        __syncthreads();

        // ---- O = O * c + P @ V  (4 rows x 16 d per thread) ----
        {
#pragma unroll
            for (int i = 0; i < 4; i++) {
                float cf = c_s[rr + i];
#pragma unroll
                for (int d = 0; d < 16; d++) O[i][d] *= cf;
            }
#pragma unroll 2
            for (int j0 = 0; j0 < 64; j0 += 4) {
                float4 pv[4];
#pragma unroll
                for (int i = 0; i < 4; i++)
                    pv[i] = *(const float4*)&Ss[(rr + i) * SS_LD + j0];
#pragma unroll
                for (int js = 0; js < 4; js++) {
                    float p[4] = {js == 0 ? pv[0].x : js == 1 ? pv[0].y : js == 2 ? pv[0].z : pv[0].w,
                                  js == 0 ? pv[1].x : js == 1 ? pv[1].y : js == 2 ? pv[1].z : pv[1].w,
                                  js == 0 ? pv[2].x : js == 1 ? pv[2].y : js == 2 ? pv[2].z : pv[2].w,
                                  js == 0 ? pv[3].x : js == 1 ? pv[3].y : js == 2 ? pv[3].z : pv[3].w};
#pragma unroll
                    for (int d4 = 0; d4 < 16; d4 += 4) {
                        float4 v = *(const float4*)&Vs[(j0 + js) * 128 + dv + d4];
#pragma unroll
                        for (int i = 0; i < 4; i++) {
                            O[i][d4 + 0] += p[i] * v.x;
                            O[i][d4 + 1] += p[i] * v.y;
                            O[i][d4 + 2] += p[i] * v.z;
                            O[i][d4 + 3] += p[i] * v.w;
                        }
                    }
                }
            }
        }
        __syncthreads();
    }

    // finalize
#pragma unroll
    for (int i = 0; i < 4; i++) {
        float inv = 1.f / l_s[rr + i];
        float* y = g_Y + (size_t)(b * SEQ_T + q0 + rr + i) * D_MODEL
                 + h * HEAD_DIM + dv;
#pragma unroll
        for (int d4 = 0; d4 < 16; d4 += 4)
            *(float4*)(y + d4) = make_float4(O[i][d4] * inv, O[i][d4 + 1] * inv,
                                             O[i][d4 + 2] * inv, O[i][d4 + 3] * inv);
    }
}

// ---------------------------------------------------------------------------
extern "C" void kernel_launch(void* const* d_in, const int* in_sizes, int n_in,
                              void* d_out, int out_size) {
    const float* x       = (const float*)d_in[0];
    const float* cosb    = (const float*)d_in[1];
    const float* sinb    = (const float*)d_in[2];
    const float* k_xl    = (const float*)d_in[3];
    const float* v_xl    = (const float*)d_in[4];
    const float* pos_emb = (const float*)d_in[5];
    const float* w_qkv   = (const float*)d_in[6];
    const float* w_proj  = (const float*)d_in[7];
    const int*   iscp    = (const int*)d_in[8];
    float* out = (float*)d_out;

    float *qkv_p = nullptr, *y_p = nullptr;
    cudaGetSymbolAddress((void**)&qkv_p, g_qkv);
    cudaGetSymbolAddress((void**)&y_p, g_Y);

    cudaFuncSetAttribute(attn_kernel,
                         cudaFuncAttributeMaxDynamicSharedMemorySize,
                         ATTN_SMEM_BYTES);

    // 1) qkv = x @ w_qkv^T   [2048 x 6144 x 2048]
    sgemm_nt<<<dim3(3 * D_MODEL / 128, M_ROWS / 128), 256>>>(
        x, w_qkv, qkv_p, M_ROWS, 3 * D_MODEL, D_MODEL);

    // 2) rope / concat / layout
    {
        int total = BATCH * SEQ_T * N_HEADS * (HEAD_DIM / 2);
        prep_kernel<<<total / 256, 256>>>(k_xl, v_xl, pos_emb, cosb, sinb);
    }

    // 3) attention (128-row Q tiles)
    attn_kernel<<<dim3(SEQ_T / 128, N_HEADS, BATCH), 256, ATTN_SMEM_BYTES>>>(iscp);

    // 4) out = y @ w_proj^T  [2048 x 2048 x 2048]
    sgemm_nt<<<dim3(D_MODEL / 128, M_ROWS / 128), 256>>>(
        y_p, w_proj, out, M_ROWS, D_MODEL, D_MODEL);
}

// round 5
// speedup vs baseline: 1.9904x; 1.3156x over previous
#include <cuda_runtime.h>
#include <cuda_bf16.h>
#include <cstdint>

// Problem constants
#define D_MODEL 2048
#define N_HEADS 16
#define HEAD_DIM 128
#define BATCH 2
#define SEQ_T 1024
#define XL_LEN 1024
#define KV_LEN (SEQ_T + XL_LEN)   // 2048
#define M_ROWS (BATCH * SEQ_T)    // 2048

// ---------------------------------------------------------------------------
// Scratch (device globals; no allocation allowed)
// ---------------------------------------------------------------------------
__device__ float g_qkv[M_ROWS * 3 * D_MODEL];
__device__ float g_Q[BATCH * N_HEADS * SEQ_T * HEAD_DIM];
__device__ float g_K[BATCH * N_HEADS * KV_LEN * HEAD_DIM];
__device__ float g_V[BATCH * N_HEADS * KV_LEN * HEAD_DIM];
__device__ float g_Y[M_ROWS * D_MODEL];

// bf16 split buffers
__device__ __nv_bfloat16 g_xh[M_ROWS * D_MODEL];
__device__ __nv_bfloat16 g_xl[M_ROWS * D_MODEL];
__device__ __nv_bfloat16 g_wqh[3 * D_MODEL * D_MODEL];
__device__ __nv_bfloat16 g_wql[3 * D_MODEL * D_MODEL];
__device__ __nv_bfloat16 g_wph[D_MODEL * D_MODEL];
__device__ __nv_bfloat16 g_wpl[D_MODEL * D_MODEL];
__device__ __nv_bfloat16 g_yh[M_ROWS * D_MODEL];
__device__ __nv_bfloat16 g_yl[M_ROWS * D_MODEL];

// ---------------------------------------------------------------------------
// Baseline-PTX tensor-core helpers (valid at compute_103: no 'a' features)
// ---------------------------------------------------------------------------
__device__ __forceinline__ uint32_t smem_u32(const void* p) {
    uint32_t a;
    asm("{ .reg .u64 t; cvta.to.shared.u64 t, %1; cvt.u32.u64 %0, t; }"
        : "=r"(a) : "l"(p));
    return a;
}
__device__ __forceinline__ void cp_async16(uint32_t saddr, const void* gaddr) {
    asm volatile("cp.async.cg.shared.global [%0], [%1], 16;"
                 :: "r"(saddr), "l"(gaddr));
}
#define CP_COMMIT() asm volatile("cp.async.commit_group;" ::: "memory")
#define CP_WAIT0()  asm volatile("cp.async.wait_group 0;" ::: "memory")

__device__ __forceinline__ void ldsm4(uint32_t* r, uint32_t a) {
    asm volatile("ldmatrix.sync.aligned.m8n8.x4.shared.b16 {%0,%1,%2,%3}, [%4];"
                 : "=r"(r[0]), "=r"(r[1]), "=r"(r[2]), "=r"(r[3]) : "r"(a));
}
__device__ __forceinline__ void mma_bf16(float* c, const uint32_t* a,
                                         uint32_t b0, uint32_t b1) {
    asm volatile(
        "mma.sync.aligned.m16n8k16.row.col.f32.bf16.bf16.f32 "
        "{%0,%1,%2,%3}, {%4,%5,%6,%7}, {%8,%9}, {%0,%1,%2,%3};"
        : "+f"(c[0]), "+f"(c[1]), "+f"(c[2]), "+f"(c[3])
        : "r"(a[0]), "r"(a[1]), "r"(a[2]), "r"(a[3]), "r"(b0), "r"(b1));
}

// ---------------------------------------------------------------------------
// fp32 -> (bf16 hi, bf16 lo) split
// ---------------------------------------------------------------------------
__global__ void split_kernel(const float* __restrict__ in,
                             __nv_bfloat16* __restrict__ hi,
                             __nv_bfloat16* __restrict__ lo, int n) {
    int i = (blockIdx.x * blockDim.x + threadIdx.x) * 4;
    if (i >= n) return;
    float4 v = *(const float4*)(in + i);
    __nv_bfloat16 h[4], l[4];
    h[0] = __float2bfloat16(v.x); h[1] = __float2bfloat16(v.y);
    h[2] = __float2bfloat16(v.z); h[3] = __float2bfloat16(v.w);
    l[0] = __float2bfloat16(v.x - __bfloat162float(h[0]));
    l[1] = __float2bfloat16(v.y - __bfloat162float(h[1]));
    l[2] = __float2bfloat16(v.z - __bfloat162float(h[2]));
    l[3] = __float2bfloat16(v.w - __bfloat162float(h[3]));
    *(uint2*)(hi + i) = *(uint2*)h;
    *(uint2*)(lo + i) = *(uint2*)l;
}

// ---------------------------------------------------------------------------
// Warp-MMA split-bf16 GEMM (NT): C[M,N] = A[M,K] @ B[N,K]^T (fp32 result)
// C = Ah Bh^T + Ah Bl^T + Al Bh^T, fp32 accumulators in registers.
// 128x128 CTA tile, BK=32, 8 warps (2m x 4n), cp.async double buffer.
// SMEM rows padded: LDA = 40 bf16 (80 B) -> conflict-free ldmatrix.
// ---------------------------------------------------------------------------
#define GEMM_LDA 40
#define GEMM_TILE_B (128 * GEMM_LDA * 2)     // 10240 B per tile
#define GEMM_STAGE_B (4 * GEMM_TILE_B)       // Ah, Al, Bh, Bl
#define GEMM_SMEM_B (2 * GEMM_STAGE_B)       // 81920 B

__global__ __launch_bounds__(256, 1)
void mma_gemm(const __nv_bfloat16* __restrict__ Ah, const __nv_bfloat16* __restrict__ Al,
              const __nv_bfloat16* __restrict__ Bh, const __nv_bfloat16* __restrict__ Bl,
              float* __restrict__ C, int M, int N, int K) {
    extern __shared__ __align__(1024) char dsm[];
    const uint32_t sb0 = smem_u32(dsm);

    const int tid = threadIdx.x;
    const int wid = tid >> 5;
    const int lane = tid & 31;
    const int bm = blockIdx.y * 128;
    const int bn = blockIdx.x * 128;

    const int wm = (wid & 1) * 64;        // warp M offset in tile
    const int wn = (wid >> 1) * 32;       // warp N offset in tile

    // global load mapping: 2 uint4 per tile per thread
    const int r_ld = tid >> 1;                 // row 0..127
    const int u0 = (tid & 1) * 2;              // 16B units {0,1} or {2,3}

    auto load_chunk = [&](int c, int buf) {
        uint32_t s = sb0 + buf * GEMM_STAGE_B;
        const __nv_bfloat16* gA = Ah + (size_t)(bm + r_ld) * K + c * 32;
        const __nv_bfloat16* gAl = Al + (size_t)(bm + r_ld) * K + c * 32;
        const __nv_bfloat16* gB = Bh + (size_t)(bn + r_ld) * K + c * 32;
        const __nv_bfloat16* gBl = Bl + (size_t)(bn + r_ld) * K + c * 32;
        uint32_t so = (uint32_t)(r_ld * 80 + u0 * 16);
#pragma unroll
        for (int t = 0; t < 2; t++) {
            uint32_t o = so + t * 16;
            int e = (u0 + t) * 8;
            cp_async16(s + 0 * GEMM_TILE_B + o, gA + e);
            cp_async16(s + 1 * GEMM_TILE_B + o, gAl + e);
            cp_async16(s + 2 * GEMM_TILE_B + o, gB + e);
            cp_async16(s + 3 * GEMM_TILE_B + o, gBl + e);
        }
    };

    float acc[4][4][4];
#pragma unroll
    for (int i = 0; i < 4; i++)
#pragma unroll
        for (int j = 0; j < 4; j++)
#pragma unroll
            for (int e = 0; e < 4; e++) acc[i][j][e] = 0.f;

    const int nk = K >> 5;
    load_chunk(0, 0);
    CP_COMMIT();

    // ldmatrix address components (bytes)
    const int a_row = (lane & 15);            // row within m16
    const int a_koff = (lane >> 4) * 8;       // k half
    const int b_nrow = (lane & 7) + ((lane >> 4) << 3);  // n within 16
    const int b_koff = ((lane >> 3) & 1) * 8;

    for (int c = 0; c < nk; c++) {
        const int buf = c & 1;
        CP_WAIT0();
        __syncthreads();
        if (c + 1 < nk) { load_chunk(c + 1, buf ^ 1); CP_COMMIT(); }

        const uint32_t s = sb0 + buf * GEMM_STAGE_B;
        const uint32_t sAh = s;
        const uint32_t sAl = s + GEMM_TILE_B;
        const uint32_t sBh = s + 2 * GEMM_TILE_B;
        const uint32_t sBl = s + 3 * GEMM_TILE_B;

#pragma unroll
        for (int ks = 0; ks < 2; ks++) {
            const int kb = ks * 16;
            uint32_t ah[4][4], al[4][4], bh[2][4], bl[2][4];
#pragma unroll
            for (int mf = 0; mf < 4; mf++) {
                uint32_t off = (uint32_t)((wm + mf * 16 + a_row) * 80 +
                                          (kb + a_koff) * 2);
                ldsm4(ah[mf], sAh + off);
                ldsm4(al[mf], sAl + off);
            }
#pragma unroll
            for (int nf = 0; nf < 2; nf++) {
                uint32_t off = (uint32_t)((wn + nf * 16 + b_nrow) * 80 +
                                          (kb + b_koff) * 2);
                ldsm4(bh[nf], sBh + off);
                ldsm4(bl[nf], sBl + off);
            }
#pragma unroll
            for (int mf = 0; mf < 4; mf++)
#pragma unroll
                for (int n = 0; n < 4; n++) {
                    const int f2 = n >> 1, j = (n & 1) * 2;
                    mma_bf16(acc[mf][n], ah[mf], bh[f2][j], bh[f2][j + 1]);
                    mma_bf16(acc[mf][n], ah[mf], bl[f2][j], bl[f2][j + 1]);
                    mma_bf16(acc[mf][n], al[mf], bh[f2][j], bh[f2][j + 1]);
                }
        }
        __syncthreads();
    }

    // epilogue
    const int g = lane >> 2, tig = lane & 3;
#pragma unroll
    for (int mf = 0; mf < 4; mf++) {
#pragma unroll
        for (int n = 0; n < 4; n++) {
            int row0 = bm + wm + mf * 16 + g;
            int col = bn + wn + n * 8 + tig * 2;
            *(float2*)(C + (size_t)row0 * N + col) =
                make_float2(acc[mf][n][0], acc[mf][n][1]);
            *(float2*)(C + (size_t)(row0 + 8) * N + col) =
                make_float2(acc[mf][n][2], acc[mf][n][3]);
        }
    }
}

// ---------------------------------------------------------------------------
// Prep: RoPE(q) -> g_Q; RoPE(k_cur) -> g_K[.., XL+t]; k_xl+pos -> g_K[.., t];
//       v -> g_V.
// ---------------------------------------------------------------------------
__global__ void prep_kernel(const float* __restrict__ k_xl,
                            const float* __restrict__ v_xl,
                            const float* __restrict__ pos_emb,
                            const float* __restrict__ cosb,
                            const float* __restrict__ sinb) {
    int idx = blockIdx.x * blockDim.x + threadIdx.x;
    int i = idx & 63;
    int h = (idx >> 6) & (N_HEADS - 1);
    int t = (idx >> 10) & (SEQ_T - 1);
    int b = idx >> 20;
    if (b >= BATCH) return;

    int m = b * SEQ_T + t;
    float c = cosb[t * 64 + i];
    float s = sinb[t * 64 + i];
    int d0 = 2 * i;

    const float* qk_row = g_qkv + (size_t)m * (3 * D_MODEL);

    {
        float2 xv = *(const float2*)(qk_row + h * HEAD_DIM + d0);
        float2 o;
        o.x = xv.x * c - xv.y * s;
        o.y = xv.x * s + xv.y * c;
        int base = ((b * N_HEADS + h) * SEQ_T + t) * HEAD_DIM + d0;
        *(float2*)(g_Q + base) = o;
    }
    {
        float2 xv = *(const float2*)(qk_row + D_MODEL + h * HEAD_DIM + d0);
        float2 o;
        o.x = xv.x * c - xv.y * s;
        o.y = xv.x * s + xv.y * c;
        int base = ((b * N_HEADS + h) * KV_LEN + XL_LEN + t) * HEAD_DIM + d0;
        *(float2*)(g_K + base) = o;
    }
    {
        float2 xv = *(const float2*)(qk_row + 2 * D_MODEL + h * HEAD_DIM + d0);
        int base = ((b * N_HEADS + h) * KV_LEN + XL_LEN + t) * HEAD_DIM + d0;
        *(float2*)(g_V + base) = xv;
    }
    {
        int src = (b * XL_LEN + t) * D_MODEL + h * HEAD_DIM + d0;
        int psrc = t * D_MODEL + h * HEAD_DIM + d0;
        float2 kv = *(const float2*)(k_xl + src);
        float2 pv = *(const float2*)(pos_emb + psrc);
        float2 vv = *(const float2*)(v_xl + src);
        float2 ko; ko.x = kv.x + pv.x; ko.y = kv.y + pv.y;
        int base = ((b * N_HEADS + h) * KV_LEN + t) * HEAD_DIM + d0;
        *(float2*)(g_K + base) = ko;
        *(float2*)(g_V + base) = vv;
    }
}

// ---------------------------------------------------------------------------
// Flash attention, fp32. 128-row Q tile per block, 256 threads.
// ---------------------------------------------------------------------------
#define SS_LD 68
constexpr int ATTN_SMEM_FLOATS =
    128 * 132 + 64 * 132 + 64 * 128 + 128 * SS_LD + 3 * 128;
constexpr int ATTN_SMEM_BYTES = ATTN_SMEM_FLOATS * 4;

__global__ __launch_bounds__(256, 1)
void attn_kernel(const int* __restrict__ iscp) {
    extern __shared__ float sm[];
    float* Qs  = sm;
    float* Ks  = Qs + 128 * 132;
    float* Vs  = Ks + 64 * 132;
    float* Ss  = Vs + 64 * 128;
    float* m_s = Ss + 128 * SS_LD;
    float* l_s = m_s + 128;
    float* c_s = l_s + 128;

    const int tid = threadIdx.x;
    const int q0 = blockIdx.x * 128;
    const int h = blockIdx.y;
    const int b = blockIdx.z;
    const bool causal = (*iscp) != 0;
    const float scale = 0.08838834764831845f;
    const int diag = KV_LEN - SEQ_T;

    const float* Qg = g_Q + (size_t)(b * N_HEADS + h) * SEQ_T * HEAD_DIM;
    const float* Kg = g_K + (size_t)(b * N_HEADS + h) * KV_LEN * HEAD_DIM;
    const float* Vg = g_V + (size_t)(b * N_HEADS + h) * KV_LEN * HEAD_DIM;

#pragma unroll
    for (int it = 0; it < 16; it++) {
        int idx = tid + it * 256;
        int r = idx >> 5;
        int c4 = (idx & 31) * 4;
        float4 q = *(const float4*)(Qg + (size_t)(q0 + r) * HEAD_DIM + c4);
        q.x *= scale; q.y *= scale; q.z *= scale; q.w *= scale;
        *(float4*)&Qs[r * 132 + c4] = q;
    }
    if (tid < 128) { m_s[tid] = -1e30f; l_s[tid] = 0.f; }

    const int ty = tid >> 4;
    const int tx = tid & 15;
    const int rr = (tid >> 3) * 4;
    const int dv = (tid & 7) * 16;

    float O[4][16];
#pragma unroll
    for (int i = 0; i < 4; i++)
#pragma unroll
        for (int d = 0; d < 16; d++) O[i][d] = 0.f;

    __syncthreads();

    for (int kc = 0; kc < KV_LEN; kc += 64) {
#pragma unroll
        for (int it = 0; it < 8; it++) {
            int idx = tid + it * 256;
            int r = idx >> 5;
            int c4 = (idx & 31) * 4;
            *(float4*)&Ks[r * 132 + c4] =
                *(const float4*)(Kg + (size_t)(kc + r) * HEAD_DIM + c4);
            *(float4*)&Vs[r * 128 + c4] =
                *(const float4*)(Vg + (size_t)(kc + r) * HEAD_DIM + c4);
        }
        __syncthreads();

        float sacc[8][4];
#pragma unroll
        for (int i = 0; i < 8; i++)
#pragma unroll
            for (int j = 0; j < 4; j++) sacc[i][j] = 0.f;

#pragma unroll 2
        for (int dd = 0; dd < HEAD_DIM; dd += 4) {
            float4 bb[4];
#pragma unroll
            for (int j = 0; j < 4; j++)
                bb[j] = *(const float4*)&Ks[(tx * 4 + j) * 132 + dd];
#pragma unroll
            for (int i = 0; i < 8; i++) {
                float4 a = *(const float4*)&Qs[(ty * 8 + i) * 132 + dd];
#pragma unroll
                for (int j = 0; j < 4; j++) {
                    sacc[i][j] += a.x * bb[j].x;
                    sacc[i][j] += a.y * bb[j].y;
                    sacc[i][j] += a.z * bb[j].z;
                    sacc[i][j] += a.w * bb[j].w;
                }
            }
        }

        if (causal) {
#pragma unroll
            for (int i = 0; i < 8; i++)
#pragma unroll
                for (int j = 0; j < 4; j++)
                    if ((kc + tx * 4 + j) > (q0 + ty * 8 + i) + diag)
                        sacc[i][j] = -1e30f;
        }

#pragma unroll
        for (int i = 0; i < 8; i++) {
            int row = ty * 8 + i;
            float mx = fmaxf(fmaxf(sacc[i][0], sacc[i][1]),
                             fmaxf(sacc[i][2], sacc[i][3]));
            mx = fmaxf(mx, __shfl_xor_sync(0xffffffffu, mx, 1));
            mx = fmaxf(mx, __shfl_xor_sync(0xffffffffu, mx, 2));
            mx = fmaxf(mx, __shfl_xor_sync(0xffffffffu, mx, 4));
            mx = fmaxf(mx, __shfl_xor_sync(0xffffffffu, mx, 8));
            float m_old = m_s[row];
            float m_new = fmaxf(m_old, mx);
            float4 p;
            p.x = __expf(sacc[i][0] - m_new);
            p.y = __expf(sacc[i][1] - m_new);
            p.z = __expf(sacc[i][2] - m_new);
            p.w = __expf(sacc[i][3] - m_new);
            float sum = (p.x + p.y) + (p.z + p.w);
            sum += __shfl_xor_sync(0xffffffffu, sum, 1);
            sum += __shfl_xor_sync(0xffffffffu, sum, 2);
            sum += __shfl_xor_sync(0xffffffffu, sum, 4);
            sum += __shfl_xor_sync(0xffffffffu, sum, 8);
            *(float4*)&Ss[row * SS_LD + tx * 4] = p;
            if (tx == 0) {
                float cf = __expf(m_old - m_new);
                l_s[row] = l_s[row] * cf + sum;
                m_s[row] = m_new;
                c_s[row] = cf;
            }
        }
        __syncthreads();

        {
#pragma unroll
            for (int i = 0; i < 4; i++) {
                float cf = c_s[rr + i];
#pragma unroll
                for (int d = 0; d < 16; d++) O[i][d] *= cf;
            }
#pragma unroll 2
            for (int j0 = 0; j0 < 64; j0 += 4) {
                float4 pv[4];
#pragma unroll
                for (int i = 0; i < 4; i++)
                    pv[i] = *(const float4*)&Ss[(rr + i) * SS_LD + j0];
#pragma unroll
                for (int js = 0; js < 4; js++) {
                    float p[4] = {js == 0 ? pv[0].x : js == 1 ? pv[0].y : js == 2 ? pv[0].z : pv[0].w,
                                  js == 0 ? pv[1].x : js == 1 ? pv[1].y : js == 2 ? pv[1].z : pv[1].w,
                                  js == 0 ? pv[2].x : js == 1 ? pv[2].y : js == 2 ? pv[2].z : pv[2].w,
                                  js == 0 ? pv[3].x : js == 1 ? pv[3].y : js == 2 ? pv[3].z : pv[3].w};
#pragma unroll
                    for (int d4 = 0; d4 < 16; d4 += 4) {
                        float4 v = *(const float4*)&Vs[(j0 + js) * 128 + dv + d4];
#pragma unroll
                        for (int i = 0; i < 4; i++) {
                            O[i][d4 + 0] += p[i] * v.x;
                            O[i][d4 + 1] += p[i] * v.y;
                            O[i][d4 + 2] += p[i] * v.z;
                            O[i][d4 + 3] += p[i] * v.w;
                        }
                    }
                }
            }
        }
        __syncthreads();
    }

#pragma unroll
    for (int i = 0; i < 4; i++) {
        float inv = 1.f / l_s[rr + i];
        float* y = g_Y + (size_t)(b * SEQ_T + q0 + rr + i) * D_MODEL
                 + h * HEAD_DIM + dv;
#pragma unroll
        for (int d4 = 0; d4 < 16; d4 += 4)
            *(float4*)(y + d4) = make_float4(O[i][d4] * inv, O[i][d4 + 1] * inv,
                                             O[i][d4 + 2] * inv, O[i][d4 + 3] * inv);
    }
}

// ---------------------------------------------------------------------------
extern "C" void kernel_launch(void* const* d_in, const int* in_sizes, int n_in,
                              void* d_out, int out_size) {
    const float* x       = (const float*)d_in[0];
    const float* cosb    = (const float*)d_in[1];
    const float* sinb    = (const float*)d_in[2];
    const float* k_xl    = (const float*)d_in[3];
    const float* v_xl    = (const float*)d_in[4];
    const float* pos_emb = (const float*)d_in[5];
    const float* w_qkv   = (const float*)d_in[6];
    const float* w_proj  = (const float*)d_in[7];
    const int*   iscp    = (const int*)d_in[8];
    float* out = (float*)d_out;

    float *qkv_p, *y_p;
    __nv_bfloat16 *xh, *xl, *wqh, *wql, *wph, *wpl, *yh, *yl;
    cudaGetSymbolAddress((void**)&qkv_p, g_qkv);
    cudaGetSymbolAddress((void**)&y_p, g_Y);
    cudaGetSymbolAddress((void**)&xh, g_xh);
    cudaGetSymbolAddress((void**)&xl, g_xl);
    cudaGetSymbolAddress((void**)&wqh, g_wqh);
    cudaGetSymbolAddress((void**)&wql, g_wql);
    cudaGetSymbolAddress((void**)&wph, g_wph);
    cudaGetSymbolAddress((void**)&wpl, g_wpl);
    cudaGetSymbolAddress((void**)&yh, g_yh);
    cudaGetSymbolAddress((void**)&yl, g_yl);

    cudaFuncSetAttribute(attn_kernel,
                         cudaFuncAttributeMaxDynamicSharedMemorySize,
                         ATTN_SMEM_BYTES);
    cudaFuncSetAttribute(mma_gemm,
                         cudaFuncAttributeMaxDynamicSharedMemorySize,
                         GEMM_SMEM_B);

    // 0) split x / w_qkv / w_proj into bf16 hi+lo
    {
        int nx = M_ROWS * D_MODEL;
        int nwq = 3 * D_MODEL * D_MODEL;
        int nwp = D_MODEL * D_MODEL;
        split_kernel<<<nx / 1024, 256>>>(x, xh, xl, nx);
        split_kernel<<<nwq / 1024, 256>>>(w_qkv, wqh, wql, nwq);
        split_kernel<<<nwp / 1024, 256>>>(w_proj, wph, wpl, nwp);
    }

    // 1) qkv = x @ w_qkv^T  (warp-MMA split bf16)  [2048 x 6144 x 2048]
    mma_gemm<<<dim3(3 * D_MODEL / 128, M_ROWS / 128), 256, GEMM_SMEM_B>>>(
        xh, xl, wqh, wql, qkv_p, M_ROWS, 3 * D_MODEL, D_MODEL);

    // 2) rope / concat / layout
    {
        int total = BATCH * SEQ_T * N_HEADS * (HEAD_DIM / 2);
        prep_kernel<<<total / 256, 256>>>(k_xl, v_xl, pos_emb, cosb, sinb);
    }

    // 3) attention (fp32 flash)
    attn_kernel<<<dim3(SEQ_T / 128, N_HEADS, BATCH), 256, ATTN_SMEM_BYTES>>>(iscp);

    // 4) split y, then out = y @ w_proj^T  [2048 x 2048 x 2048]
    {
        int ny = M_ROWS * D_MODEL;
        split_kernel<<<ny / 1024, 256>>>(y_p, yh, yl, ny);
    }
    mma_gemm<<<dim3(D_MODEL / 128, M_ROWS / 128), 256, GEMM_SMEM_B>>>(
        yh, yl, wph, wpl, out, M_ROWS, D_MODEL, D_MODEL);
}

// round 10
// speedup vs baseline: 3.3197x; 1.6679x over previous
#include <cuda_runtime.h>
#include <cuda_bf16.h>
#include <cstdint>

// Problem constants
#define D_MODEL 2048
#define N_HEADS 16
#define HEAD_DIM 128
#define BATCH 2
#define SEQ_T 1024
#define XL_LEN 1024
#define KV_LEN (SEQ_T + XL_LEN)   // 2048
#define M_ROWS (BATCH * SEQ_T)    // 2048

// ---------------------------------------------------------------------------
// Scratch (device globals; no allocation allowed)
// ---------------------------------------------------------------------------
__device__ float g_qkv[M_ROWS * 3 * D_MODEL];

// bf16 split buffers for GEMMs
__device__ __nv_bfloat16 g_xh[M_ROWS * D_MODEL];
__device__ __nv_bfloat16 g_xl[M_ROWS * D_MODEL];
__device__ __nv_bfloat16 g_wqh[3 * D_MODEL * D_MODEL];
__device__ __nv_bfloat16 g_wql[3 * D_MODEL * D_MODEL];
__device__ __nv_bfloat16 g_wph[D_MODEL * D_MODEL];
__device__ __nv_bfloat16 g_wpl[D_MODEL * D_MODEL];
__device__ __nv_bfloat16 g_yh[M_ROWS * D_MODEL];
__device__ __nv_bfloat16 g_yl[M_ROWS * D_MODEL];

// bf16 split buffers for attention
__device__ __nv_bfloat16 g_Qh[BATCH * N_HEADS * SEQ_T * HEAD_DIM];
__device__ __nv_bfloat16 g_Ql[BATCH * N_HEADS * SEQ_T * HEAD_DIM];
__device__ __nv_bfloat16 g_Kh[BATCH * N_HEADS * KV_LEN * HEAD_DIM];
__device__ __nv_bfloat16 g_Kl[BATCH * N_HEADS * KV_LEN * HEAD_DIM];
__device__ __nv_bfloat16 g_Vh[BATCH * N_HEADS * KV_LEN * HEAD_DIM];
__device__ __nv_bfloat16 g_Vl[BATCH * N_HEADS * KV_LEN * HEAD_DIM];

// ---------------------------------------------------------------------------
// Baseline-PTX tensor-core helpers (valid at compute_103: no 'a' features)
// ---------------------------------------------------------------------------
__device__ __forceinline__ uint32_t smem_u32(const void* p) {
    uint32_t a;
    asm("{ .reg .u64 t; cvta.to.shared.u64 t, %1; cvt.u32.u64 %0, t; }"
        : "=r"(a) : "l"(p));
    return a;
}
__device__ __forceinline__ void cp_async16(uint32_t saddr, const void* gaddr) {
    asm volatile("cp.async.cg.shared.global [%0], [%1], 16;"
                 :: "r"(saddr), "l"(gaddr));
}
#define CP_COMMIT() asm volatile("cp.async.commit_group;" ::: "memory")
#define CP_WAIT0()  asm volatile("cp.async.wait_group 0;" ::: "memory")
#define CP_WAIT1()  asm volatile("cp.async.wait_group 1;" ::: "memory")

__device__ __forceinline__ void ldsm4(uint32_t* r, uint32_t a) {
    asm volatile("ldmatrix.sync.aligned.m8n8.x4.shared.b16 {%0,%1,%2,%3}, [%4];"
                 : "=r"(r[0]), "=r"(r[1]), "=r"(r[2]), "=r"(r[3]) : "r"(a));
}
__device__ __forceinline__ void ldsm4t(uint32_t* r, uint32_t a) {
    asm volatile("ldmatrix.sync.aligned.m8n8.x4.trans.shared.b16 {%0,%1,%2,%3}, [%4];"
                 : "=r"(r[0]), "=r"(r[1]), "=r"(r[2]), "=r"(r[3]) : "r"(a));
}
__device__ __forceinline__ void mma_bf16(float* c, const uint32_t* a,
                                         uint32_t b0, uint32_t b1) {
    asm volatile(
        "mma.sync.aligned.m16n8k16.row.col.f32.bf16.bf16.f32 "
        "{%0,%1,%2,%3}, {%4,%5,%6,%7}, {%8,%9}, {%0,%1,%2,%3};"
        : "+f"(c[0]), "+f"(c[1]), "+f"(c[2]), "+f"(c[3])
        : "r"(a[0]), "r"(a[1]), "r"(a[2]), "r"(a[3]), "r"(b0), "r"(b1));
}

// pack 2 floats to bf16x2 (hi) and return residuals
__device__ __forceinline__ uint32_t pack_hi(float a, float b, float& ra, float& rb) {
    __nv_bfloat162 hh = __floats2bfloat162_rn(a, b);
    float2 f = __bfloat1622float2(hh);
    ra = a - f.x; rb = b - f.y;
    return *(uint32_t*)&hh;
}
__device__ __forceinline__ uint32_t pack2(float a, float b) {
    __nv_bfloat162 hh = __floats2bfloat162_rn(a, b);
    return *(uint32_t*)&hh;
}
__device__ __forceinline__ void split2(float a, float b,
                                       __nv_bfloat162& hp, __nv_bfloat162& lp) {
    hp = __floats2bfloat162_rn(a, b);
    float2 f = __bfloat1622float2(hp);
    lp = __floats2bfloat162_rn(a - f.x, b - f.y);
}

// ---------------------------------------------------------------------------
// fp32 -> (bf16 hi, bf16 lo) split
// ---------------------------------------------------------------------------
__global__ void split_kernel(const float* __restrict__ in,
                             __nv_bfloat16* __restrict__ hi,
                             __nv_bfloat16* __restrict__ lo, int n) {
    int i = (blockIdx.x * blockDim.x + threadIdx.x) * 4;
    if (i >= n) return;
    float4 v = *(const float4*)(in + i);
    __nv_bfloat16 h[4], l[4];
    h[0] = __float2bfloat16(v.x); h[1] = __float2bfloat16(v.y);
    h[2] = __float2bfloat16(v.z); h[3] = __float2bfloat16(v.w);
    l[0] = __float2bfloat16(v.x - __bfloat162float(h[0]));
    l[1] = __float2bfloat16(v.y - __bfloat162float(h[1]));
    l[2] = __float2bfloat16(v.z - __bfloat162float(h[2]));
    l[3] = __float2bfloat16(v.w - __bfloat162float(h[3]));
    *(uint2*)(hi + i) = *(uint2*)h;
    *(uint2*)(lo + i) = *(uint2*)l;
}

// ---------------------------------------------------------------------------
// Warp-MMA split-bf16 GEMM (NT): C[M,N] = A[M,K] @ B[N,K]^T (fp32 result)
// ---------------------------------------------------------------------------
#define GEMM_LDA 40
#define GEMM_TILE_B (128 * GEMM_LDA * 2)     // 10240 B per tile
#define GEMM_STAGE_B (4 * GEMM_TILE_B)
#define GEMM_SMEM_B (2 * GEMM_STAGE_B)       // 81920 B

__global__ __launch_bounds__(256, 2)
void mma_gemm(const __nv_bfloat16* __restrict__ Ah, const __nv_bfloat16* __restrict__ Al,
              const __nv_bfloat16* __restrict__ Bh, const __nv_bfloat16* __restrict__ Bl,
              float* __restrict__ C, int M, int N, int K) {
    extern __shared__ __align__(1024) char dsm[];
    const uint32_t sb0 = smem_u32(dsm);

    const int tid = threadIdx.x;
    const int wid = tid >> 5;
    const int lane = tid & 31;
    const int bm = blockIdx.y * 128;
    const int bn = blockIdx.x * 128;

    const int wm = (wid & 1) * 64;
    const int wn = (wid >> 1) * 32;

    const int r_ld = tid >> 1;
    const int u0 = (tid & 1) * 2;

    auto load_chunk = [&](int c, int buf) {
        uint32_t s = sb0 + buf * GEMM_STAGE_B;
        const __nv_bfloat16* gA = Ah + (size_t)(bm + r_ld) * K + c * 32;
        const __nv_bfloat16* gAl = Al + (size_t)(bm + r_ld) * K + c * 32;
        const __nv_bfloat16* gB = Bh + (size_t)(bn + r_ld) * K + c * 32;
        const __nv_bfloat16* gBl = Bl + (size_t)(bn + r_ld) * K + c * 32;
        uint32_t so = (uint32_t)(r_ld * 80 + u0 * 16);
#pragma unroll
        for (int t = 0; t < 2; t++) {
            uint32_t o = so + t * 16;
            int e = (u0 + t) * 8;
            cp_async16(s + 0 * GEMM_TILE_B + o, gA + e);
            cp_async16(s + 1 * GEMM_TILE_B + o, gAl + e);
            cp_async16(s + 2 * GEMM_TILE_B + o, gB + e);
            cp_async16(s + 3 * GEMM_TILE_B + o, gBl + e);
        }
    };

    float acc[4][4][4];
#pragma unroll
    for (int i = 0; i < 4; i++)
#pragma unroll
        for (int j = 0; j < 4; j++)
#pragma unroll
            for (int e = 0; e < 4; e++) acc[i][j][e] = 0.f;

    const int nk = K >> 5;
    load_chunk(0, 0);
    CP_COMMIT();

    const int a_row = (lane & 15);
    const int a_koff = (lane >> 4) * 8;
    const int b_nrow = (lane & 7) + ((lane >> 4) << 3);
    const int b_koff = ((lane >> 3) & 1) * 8;

    for (int c = 0; c < nk; c++) {
        const int buf = c & 1;
        CP_WAIT0();
        __syncthreads();
        if (c + 1 < nk) { load_chunk(c + 1, buf ^ 1); CP_COMMIT(); }

        const uint32_t s = sb0 + buf * GEMM_STAGE_B;
        const uint32_t sAh = s;
        const uint32_t sAl = s + GEMM_TILE_B;
        const uint32_t sBh = s + 2 * GEMM_TILE_B;
        const uint32_t sBl = s + 3 * GEMM_TILE_B;

#pragma unroll
        for (int ks = 0; ks < 2; ks++) {
            const int kb = ks * 16;
            uint32_t ah[4][4], al[4][4], bh[2][4], bl[2][4];
#pragma unroll
            for (int mf = 0; mf < 4; mf++) {
                uint32_t off = (uint32_t)((wm + mf * 16 + a_row) * 80 +
                                          (kb + a_koff) * 2);
                ldsm4(ah[mf], sAh + off);
                ldsm4(al[mf], sAl + off);
            }
#pragma unroll
            for (int nf = 0; nf < 2; nf++) {
                uint32_t off = (uint32_t)((wn + nf * 16 + b_nrow) * 80 +
                                          (kb + b_koff) * 2);
                ldsm4(bh[nf], sBh + off);
                ldsm4(bl[nf], sBl + off);
            }
#pragma unroll
            for (int mf = 0; mf < 4; mf++)
#pragma unroll
                for (int n = 0; n < 4; n++) {
                    const int f2 = n >> 1, j = (n & 1) * 2;
                    mma_bf16(acc[mf][n], ah[mf], bh[f2][j], bh[f2][j + 1]);
                    mma_bf16(acc[mf][n], ah[mf], bl[f2][j], bl[f2][j + 1]);
                    mma_bf16(acc[mf][n], al[mf], bh[f2][j], bh[f2][j + 1]);
                }
        }
        __syncthreads();
    }

    const int g = lane >> 2, tig = lane & 3;
#pragma unroll
    for (int mf = 0; mf < 4; mf++) {
#pragma unroll
        for (int n = 0; n < 4; n++) {
            int row0 = bm + wm + mf * 16 + g;
            int col = bn + wn + n * 8 + tig * 2;
            *(float2*)(C + (size_t)row0 * N + col) =
                make_float2(acc[mf][n][0], acc[mf][n][1]);
            *(float2*)(C + (size_t)(row0 + 8) * N + col) =
                make_float2(acc[mf][n][2], acc[mf][n][3]);
        }
    }
}

// ---------------------------------------------------------------------------
// Prep: RoPE(q)*scale -> Qh/Ql; RoPE(k_cur) -> Kh/Kl[.., XL+t];
//       k_xl+pos -> Kh/Kl[.., t]; v -> Vh/Vl. All bf16 hi/lo splits.
// ---------------------------------------------------------------------------
__global__ void prep_kernel(const float* __restrict__ k_xl,
                            const float* __restrict__ v_xl,
                            const float* __restrict__ pos_emb,
                            const float* __restrict__ cosb,
                            const float* __restrict__ sinb) {
    int idx = blockIdx.x * blockDim.x + threadIdx.x;
    int i = idx & 63;
    int h = (idx >> 6) & (N_HEADS - 1);
    int t = (idx >> 10) & (SEQ_T - 1);
    int b = idx >> 20;
    if (b >= BATCH) return;

    const float scale = 0.08838834764831845f;  // 1/sqrt(128)
    int m = b * SEQ_T + t;
    float c = cosb[t * 64 + i];
    float s = sinb[t * 64 + i];
    int d0 = 2 * i;

    const float* qk_row = g_qkv + (size_t)m * (3 * D_MODEL);
    __nv_bfloat162 hp, lp;

    // q with rope, scaled
    {
        float2 xv = *(const float2*)(qk_row + h * HEAD_DIM + d0);
        float o0 = (xv.x * c - xv.y * s) * scale;
        float o1 = (xv.x * s + xv.y * c) * scale;
        size_t base = ((size_t)(b * N_HEADS + h) * SEQ_T + t) * HEAD_DIM + d0;
        split2(o0, o1, hp, lp);
        *(__nv_bfloat162*)(g_Qh + base) = hp;
        *(__nv_bfloat162*)(g_Ql + base) = lp;
    }
    // k current with rope -> kv idx XL+t
    {
        float2 xv = *(const float2*)(qk_row + D_MODEL + h * HEAD_DIM + d0);
        float o0 = xv.x * c - xv.y * s;
        float o1 = xv.x * s + xv.y * c;
        size_t base = ((size_t)(b * N_HEADS + h) * KV_LEN + XL_LEN + t) * HEAD_DIM + d0;
        split2(o0, o1, hp, lp);
        *(__nv_bfloat162*)(g_Kh + base) = hp;
        *(__nv_bfloat162*)(g_Kl + base) = lp;
    }
    // v current
    {
        float2 xv = *(const float2*)(qk_row + 2 * D_MODEL + h * HEAD_DIM + d0);
        size_t base = ((size_t)(b * N_HEADS + h) * KV_LEN + XL_LEN + t) * HEAD_DIM + d0;
        split2(xv.x, xv.y, hp, lp);
        *(__nv_bfloat162*)(g_Vh + base) = hp;
        *(__nv_bfloat162*)(g_Vl + base) = lp;
    }
    // k_xl + pos_emb, v_xl -> kv idx t
    {
        int src = (b * XL_LEN + t) * D_MODEL + h * HEAD_DIM + d0;
        int psrc = t * D_MODEL + h * HEAD_DIM + d0;
        float2 kv = *(const float2*)(k_xl + src);
        float2 pv = *(const float2*)(pos_emb + psrc);
        float2 vv = *(const float2*)(v_xl + src);
        size_t base = ((size_t)(b * N_HEADS + h) * KV_LEN + t) * HEAD_DIM + d0;
        split2(kv.x + pv.x, kv.y + pv.y, hp, lp);
        *(__nv_bfloat162*)(g_Kh + base) = hp;
        *(__nv_bfloat162*)(g_Kl + base) = lp;
        split2(vv.x, vv.y, hp, lp);
        *(__nv_bfloat162*)(g_Vh + base) = hp;
        *(__nv_bfloat162*)(g_Vl + base) = lp;
    }
}

// ---------------------------------------------------------------------------
// Flash attention with mma.sync (split bf16). 128-row Q tile, 8 warps,
// warp owns 16 rows. KV chunks of 64, double-buffered cp.async.
// S and softmax fully in registers; P re-packed into A-fragments in-register.
// ---------------------------------------------------------------------------
#define ALD 272                 // smem row stride bytes (136 bf16)
#define QTILE_B (128 * ALD)     // 34816 B
#define KVTILE_B (64 * ALD)     // 17408 B
#define ATT_SMEM_B (2 * QTILE_B + 8 * KVTILE_B)  // 208896 B

__global__ __launch_bounds__(256, 1)
void attn_mma(const int* __restrict__ iscp) {
    extern __shared__ __align__(256) char smb[];
    const int tid = threadIdx.x;
    const int wid = tid >> 5;
    const int lane = tid & 31;
    const int q0 = blockIdx.x * 128;
    const int h = blockIdx.y;
    const int b = blockIdx.z;
    const bool causal = (*iscp) != 0;
    const int diag = KV_LEN - SEQ_T;

    const uint32_t sb = smem_u32(smb);
    const uint32_t qh_b = sb;
    const uint32_t kv_b = sb + 2 * QTILE_B;

    const __nv_bfloat16* Qhg = g_Qh + ((size_t)(b * N_HEADS + h) * SEQ_T + q0) * HEAD_DIM;
    const __nv_bfloat16* Qlg = g_Ql + ((size_t)(b * N_HEADS + h) * SEQ_T + q0) * HEAD_DIM;
    const __nv_bfloat16* Khg = g_Kh + (size_t)(b * N_HEADS + h) * KV_LEN * HEAD_DIM;
    const __nv_bfloat16* Klg = g_Kl + (size_t)(b * N_HEADS + h) * KV_LEN * HEAD_DIM;
    const __nv_bfloat16* Vhg = g_Vh + (size_t)(b * N_HEADS + h) * KV_LEN * HEAD_DIM;
    const __nv_bfloat16* Vlg = g_Vl + (size_t)(b * N_HEADS + h) * KV_LEN * HEAD_DIM;

    // load Q tiles (hi & lo): 2048 16B-units each
#pragma unroll
    for (int u = 0; u < 8; u++) {
        int idx = tid * 8 + u;
        int r = idx >> 4, un = idx & 15;
        uint32_t so = (uint32_t)(r * ALD + un * 16);
        cp_async16(qh_b + so, (const char*)Qhg + r * 256 + un * 16);
        cp_async16(qh_b + QTILE_B + so, (const char*)Qlg + r * 256 + un * 16);
    }
    CP_COMMIT();

    auto load_kv = [&](int c, int buf) {
        uint32_t base = kv_b + buf * 4 * KVTILE_B;
        const char* g0 = (const char*)(Khg + (size_t)c * 64 * HEAD_DIM);
        const char* g1 = (const char*)(Klg + (size_t)c * 64 * HEAD_DIM);
        const char* g2 = (const char*)(Vhg + (size_t)c * 64 * HEAD_DIM);
        const char* g3 = (const char*)(Vlg + (size_t)c * 64 * HEAD_DIM);
#pragma unroll
        for (int u = 0; u < 4; u++) {
            int idx = tid * 4 + u;
            int r = idx >> 4, un = idx & 15;
            uint32_t so = (uint32_t)(r * ALD + un * 16);
            uint32_t go = (uint32_t)(r * 256 + un * 16);
            cp_async16(base + 0 * KVTILE_B + so, g0 + go);
            cp_async16(base + 1 * KVTILE_B + so, g1 + go);
            cp_async16(base + 2 * KVTILE_B + so, g2 + go);
            cp_async16(base + 3 * KVTILE_B + so, g3 + go);
        }
        CP_COMMIT();
    };

    load_kv(0, 0);

    float m_lo = -1e30f, m_hi = -1e30f, l_lo = 0.f, l_hi = 0.f;
    float O[16][4];
#pragma unroll
    for (int t = 0; t < 16; t++)
#pragma unroll
        for (int e = 0; e < 4; e++) O[t][e] = 0.f;

    const int a_row = lane & 15;
    const int a_koff = (lane >> 4) * 8;
    const int b_nrow = (lane & 7) + ((lane >> 4) << 3);
    const int b_koff = ((lane >> 3) & 1) * 8;

    for (int c = 0; c < KV_LEN / 64; c++) {
        const int buf = c & 1;
        if (c + 1 < KV_LEN / 64) {
            load_kv(c + 1, buf ^ 1);
            CP_WAIT1();
        } else {
            CP_WAIT0();
        }
        __syncthreads();

        const uint32_t kh_b = kv_b + buf * 4 * KVTILE_B;
        const uint32_t vh_b = kh_b + 2 * KVTILE_B;

        // ---- S = Q K^T, 3-way split, fp32 accum ----
        float s[8][4];
#pragma unroll
        for (int t = 0; t < 8; t++)
#pragma unroll
            for (int e = 0; e < 4; e++) s[t][e] = 0.f;

#pragma unroll
        for (int ks = 0; ks < 8; ks++) {
            uint32_t qa = qh_b + (uint32_t)((wid * 16 + a_row) * ALD +
                                            (ks * 16 + a_koff) * 2);
            uint32_t qh[4], ql[4];
            ldsm4(qh, qa);
            ldsm4(ql, qa + QTILE_B);
            uint32_t kcol = (uint32_t)((ks * 16 + b_koff) * 2);
#pragma unroll
            for (int ng = 0; ng < 4; ng++) {
                uint32_t ka = kh_b + (uint32_t)((ng * 16 + b_nrow) * ALD) + kcol;
                uint32_t kh4[4], kl4[4];
                ldsm4(kh4, ka);
                ldsm4(kl4, ka + KVTILE_B);
#pragma unroll
                for (int half = 0; half < 2; half++) {
                    int t = ng * 2 + half;
                    int j = half * 2;
                    mma_bf16(s[t], qh, kh4[j], kh4[j + 1]);
                    mma_bf16(s[t], qh, kl4[j], kl4[j + 1]);
                    mma_bf16(s[t], ql, kh4[j], kh4[j + 1]);
                }
            }
        }

        // ---- mask + online softmax in registers ----
        if (causal) {
            int row_lo = q0 + wid * 16 + (lane >> 2);
#pragma unroll
            for (int t = 0; t < 8; t++) {
                int col = c * 64 + t * 8 + (lane & 3) * 2;
                if (col > row_lo + diag)         s[t][0] = -1e30f;
                if (col + 1 > row_lo + diag)     s[t][1] = -1e30f;
                if (col > row_lo + 8 + diag)     s[t][2] = -1e30f;
                if (col + 1 > row_lo + 8 + diag) s[t][3] = -1e30f;
            }
        }

        float mx_lo = -1e30f, mx_hi = -1e30f;
#pragma unroll
        for (int t = 0; t < 8; t++) {
            mx_lo = fmaxf(mx_lo, fmaxf(s[t][0], s[t][1]));
            mx_hi = fmaxf(mx_hi, fmaxf(s[t][2], s[t][3]));
        }
        mx_lo = fmaxf(mx_lo, __shfl_xor_sync(0xffffffffu, mx_lo, 1));
        mx_lo = fmaxf(mx_lo, __shfl_xor_sync(0xffffffffu, mx_lo, 2));
        mx_hi = fmaxf(mx_hi, __shfl_xor_sync(0xffffffffu, mx_hi, 1));
        mx_hi = fmaxf(mx_hi, __shfl_xor_sync(0xffffffffu, mx_hi, 2));

        float mn_lo = fmaxf(m_lo, mx_lo);
        float mn_hi = fmaxf(m_hi, mx_hi);
        float cf_lo = __expf(m_lo - mn_lo);
        float cf_hi = __expf(m_hi - mn_hi);
        m_lo = mn_lo; m_hi = mn_hi;

        float sum_lo = 0.f, sum_hi = 0.f;
#pragma unroll
        for (int t = 0; t < 8; t++) {
            s[t][0] = __expf(s[t][0] - mn_lo); sum_lo += s[t][0];
            s[t][1] = __expf(s[t][1] - mn_lo); sum_lo += s[t][1];
            s[t][2] = __expf(s[t][2] - mn_hi); sum_hi += s[t][2];
            s[t][3] = __expf(s[t][3] - mn_hi); sum_hi += s[t][3];
        }
        sum_lo += __shfl_xor_sync(0xffffffffu, sum_lo, 1);
        sum_lo += __shfl_xor_sync(0xffffffffu, sum_lo, 2);
        sum_hi += __shfl_xor_sync(0xffffffffu, sum_hi, 1);
        sum_hi += __shfl_xor_sync(0xffffffffu, sum_hi, 2);
        l_lo = l_lo * cf_lo + sum_lo;
        l_hi = l_hi * cf_hi + sum_hi;

#pragma unroll
        for (int t = 0; t < 16; t++) {
            O[t][0] *= cf_lo; O[t][1] *= cf_lo;
            O[t][2] *= cf_hi; O[t][3] *= cf_hi;
        }

        // ---- pack P into A-fragments (hi + residual lo) ----
        uint32_t ph[4][4], pl[4][4];
#pragma unroll
        for (int j = 0; j < 4; j++) {
            float ra, rb;
            ph[j][0] = pack_hi(s[2 * j][0], s[2 * j][1], ra, rb);
            pl[j][0] = pack2(ra, rb);
            ph[j][1] = pack_hi(s[2 * j][2], s[2 * j][3], ra, rb);
            pl[j][1] = pack2(ra, rb);
            ph[j][2] = pack_hi(s[2 * j + 1][0], s[2 * j + 1][1], ra, rb);
            pl[j][2] = pack2(ra, rb);
            ph[j][3] = pack_hi(s[2 * j + 1][2], s[2 * j + 1][3], ra, rb);
            pl[j][3] = pack2(ra, rb);
        }

        // ---- O += P V (3-way split), V via ldmatrix.trans ----
#pragma unroll
        for (int j = 0; j < 4; j++) {
            uint32_t vrow = (uint32_t)((j * 16 + a_row) * ALD);
#pragma unroll
            for (int dg = 0; dg < 8; dg++) {
                uint32_t va = vh_b + vrow + (uint32_t)((dg * 16 + a_koff) * 2);
                uint32_t vh4[4], vl4[4];
                ldsm4t(vh4, va);
                ldsm4t(vl4, va + KVTILE_B);
                int t0 = dg * 2, t1 = t0 + 1;
                mma_bf16(O[t0], ph[j], vh4[0], vh4[1]);
                mma_bf16(O[t1], ph[j], vh4[2], vh4[3]);
                mma_bf16(O[t0], ph[j], vl4[0], vl4[1]);
                mma_bf16(O[t1], ph[j], vl4[2], vl4[3]);
                mma_bf16(O[t0], pl[j], vh4[0], vh4[1]);
                mma_bf16(O[t1], pl[j], vh4[2], vh4[3]);
            }
        }
        __syncthreads();
    }

    // ---- epilogue: y = O / l, split to bf16 hi/lo for the proj GEMM ----
    float inv_lo = 1.f / l_lo, inv_hi = 1.f / l_hi;
    int row_lo = q0 + wid * 16 + (lane >> 2);
    int row_hi = row_lo + 8;
#pragma unroll
    for (int t = 0; t < 16; t++) {
        int col = h * HEAD_DIM + t * 8 + (lane & 3) * 2;
        __nv_bfloat162 hp, lp;
        size_t o0 = (size_t)(b * SEQ_T + row_lo) * D_MODEL + col;
        split2(O[t][0] * inv_lo, O[t][1] * inv_lo, hp, lp);
        *(__nv_bfloat162*)(g_yh + o0) = hp;
        *(__nv_bfloat162*)(g_yl + o0) = lp;
        size_t o1 = (size_t)(b * SEQ_T + row_hi) * D_MODEL + col;
        split2(O[t][2] * inv_hi, O[t][3] * inv_hi, hp, lp);
        *(__nv_bfloat162*)(g_yh + o1) = hp;
        *(__nv_bfloat162*)(g_yl + o1) = lp;
    }
}

// ---------------------------------------------------------------------------
extern "C" void kernel_launch(void* const* d_in, const int* in_sizes, int n_in,
                              void* d_out, int out_size) {
    const float* x       = (const float*)d_in[0];
    const float* cosb    = (const float*)d_in[1];
    const float* sinb    = (const float*)d_in[2];
    const float* k_xl    = (const float*)d_in[3];
    const float* v_xl    = (const float*)d_in[4];
    const float* pos_emb = (const float*)d_in[5];
    const float* w_qkv   = (const float*)d_in[6];
    const float* w_proj  = (const float*)d_in[7];
    const int*   iscp    = (const int*)d_in[8];
    float* out = (float*)d_out;

    float* qkv_p;
    __nv_bfloat16 *xh, *xl, *wqh, *wql, *wph, *wpl, *yh, *yl;
    cudaGetSymbolAddress((void**)&qkv_p, g_qkv);
    cudaGetSymbolAddress((void**)&xh, g_xh);
    cudaGetSymbolAddress((void**)&xl, g_xl);
    cudaGetSymbolAddress((void**)&wqh, g_wqh);
    cudaGetSymbolAddress((void**)&wql, g_wql);
    cudaGetSymbolAddress((void**)&wph, g_wph);
    cudaGetSymbolAddress((void**)&wpl, g_wpl);
    cudaGetSymbolAddress((void**)&yh, g_yh);
    cudaGetSymbolAddress((void**)&yl, g_yl);

    cudaFuncSetAttribute(mma_gemm,
                         cudaFuncAttributeMaxDynamicSharedMemorySize, GEMM_SMEM_B);
    cudaFuncSetAttribute(attn_mma,
                         cudaFuncAttributeMaxDynamicSharedMemorySize, ATT_SMEM_B);

    // 0) split x / w_qkv / w_proj into bf16 hi+lo
    {
        int nx = M_ROWS * D_MODEL;
        int nwq = 3 * D_MODEL * D_MODEL;
        int nwp = D_MODEL * D_MODEL;
        split_kernel<<<nx / 1024, 256>>>(x, xh, xl, nx);
        split_kernel<<<nwq / 1024, 256>>>(w_qkv, wqh, wql, nwq);
        split_kernel<<<nwp / 1024, 256>>>(w_proj, wph, wpl, nwp);
    }

    // 1) qkv = x @ w_qkv^T
    mma_gemm<<<dim3(3 * D_MODEL / 128, M_ROWS / 128), 256, GEMM_SMEM_B>>>(
        xh, xl, wqh, wql, qkv_p, M_ROWS, 3 * D_MODEL, D_MODEL);

    // 2) rope / concat / split into bf16
    {
        int total = BATCH * SEQ_T * N_HEADS * (HEAD_DIM / 2);
        prep_kernel<<<total / 256, 256>>>(k_xl, v_xl, pos_emb, cosb, sinb);
    }

    // 3) attention (tensor-core flash, split bf16)
    attn_mma<<<dim3(SEQ_T / 128, N_HEADS, BATCH), 256, ATT_SMEM_B>>>(iscp);

    // 4) out = y @ w_proj^T
    mma_gemm<<<dim3(D_MODEL / 128, M_ROWS / 128), 256, GEMM_SMEM_B>>>(
        yh, yl, wph, wpl, out, M_ROWS, D_MODEL, D_MODEL);
}

// round 15
// speedup vs baseline: 4.7348x; 1.4263x over previous
#include <cuda_runtime.h>
#include <cuda_bf16.h>
#include <cstdint>

// Problem constants
#define D_MODEL 2048
#define N_HEADS 16
#define HEAD_DIM 128
#define BATCH 2
#define SEQ_T 1024
#define XL_LEN 1024
#define KV_LEN (SEQ_T + XL_LEN)   // 2048
#define M_ROWS (BATCH * SEQ_T)    // 2048

// ---------------------------------------------------------------------------
// Scratch (device globals; no allocation allowed)
// ---------------------------------------------------------------------------
__device__ float g_qkv[M_ROWS * 3 * D_MODEL];

__device__ __nv_bfloat16 g_xh[M_ROWS * D_MODEL];
__device__ __nv_bfloat16 g_xl[M_ROWS * D_MODEL];
__device__ __nv_bfloat16 g_wqh[3 * D_MODEL * D_MODEL];
__device__ __nv_bfloat16 g_wql[3 * D_MODEL * D_MODEL];
__device__ __nv_bfloat16 g_wph[D_MODEL * D_MODEL];
__device__ __nv_bfloat16 g_wpl[D_MODEL * D_MODEL];
__device__ __nv_bfloat16 g_yh[M_ROWS * D_MODEL];
__device__ __nv_bfloat16 g_yl[M_ROWS * D_MODEL];

__device__ __nv_bfloat16 g_Qh[BATCH * N_HEADS * SEQ_T * HEAD_DIM];
__device__ __nv_bfloat16 g_Ql[BATCH * N_HEADS * SEQ_T * HEAD_DIM];
__device__ __nv_bfloat16 g_Kh[BATCH * N_HEADS * KV_LEN * HEAD_DIM];
__device__ __nv_bfloat16 g_Kl[BATCH * N_HEADS * KV_LEN * HEAD_DIM];
__device__ __nv_bfloat16 g_Vh[BATCH * N_HEADS * KV_LEN * HEAD_DIM];
__device__ __nv_bfloat16 g_Vl[BATCH * N_HEADS * KV_LEN * HEAD_DIM];

// ---------------------------------------------------------------------------
// Baseline-PTX tensor-core helpers
// ---------------------------------------------------------------------------
__device__ __forceinline__ uint32_t smem_u32(const void* p) {
    uint32_t a;
    asm("{ .reg .u64 t; cvta.to.shared.u64 t, %1; cvt.u32.u64 %0, t; }"
        : "=r"(a) : "l"(p));
    return a;
}
__device__ __forceinline__ void cp_async16(uint32_t saddr, const void* gaddr) {
    asm volatile("cp.async.cg.shared.global [%0], [%1], 16;"
                 :: "r"(saddr), "l"(gaddr));
}
#define CP_COMMIT() asm volatile("cp.async.commit_group;" ::: "memory")
#define CP_WAIT0()  asm volatile("cp.async.wait_group 0;" ::: "memory")
#define CP_WAIT1()  asm volatile("cp.async.wait_group 1;" ::: "memory")

__device__ __forceinline__ void ldsm4(uint32_t* r, uint32_t a) {
    asm volatile("ldmatrix.sync.aligned.m8n8.x4.shared.b16 {%0,%1,%2,%3}, [%4];"
                 : "=r"(r[0]), "=r"(r[1]), "=r"(r[2]), "=r"(r[3]) : "r"(a));
}
__device__ __forceinline__ void ldsm4t(uint32_t* r, uint32_t a) {
    asm volatile("ldmatrix.sync.aligned.m8n8.x4.trans.shared.b16 {%0,%1,%2,%3}, [%4];"
                 : "=r"(r[0]), "=r"(r[1]), "=r"(r[2]), "=r"(r[3]) : "r"(a));
}
__device__ __forceinline__ void mma_bf16(float* c, const uint32_t* a,
                                         uint32_t b0, uint32_t b1) {
    asm volatile(
        "mma.sync.aligned.m16n8k16.row.col.f32.bf16.bf16.f32 "
        "{%0,%1,%2,%3}, {%4,%5,%6,%7}, {%8,%9}, {%0,%1,%2,%3};"
        : "+f"(c[0]), "+f"(c[1]), "+f"(c[2]), "+f"(c[3])
        : "r"(a[0]), "r"(a[1]), "r"(a[2]), "r"(a[3]), "r"(b0), "r"(b1));
}

__device__ __forceinline__ uint32_t pack_hi(float a, float b, float& ra, float& rb) {
    __nv_bfloat162 hh = __floats2bfloat162_rn(a, b);
    float2 f = __bfloat1622float2(hh);
    ra = a - f.x; rb = b - f.y;
    return *(uint32_t*)&hh;
}
__device__ __forceinline__ uint32_t pack2(float a, float b) {
    __nv_bfloat162 hh = __floats2bfloat162_rn(a, b);
    return *(uint32_t*)&hh;
}
__device__ __forceinline__ void split2(float a, float b,
                                       __nv_bfloat162& hp, __nv_bfloat162& lp) {
    hp = __floats2bfloat162_rn(a, b);
    float2 f = __bfloat1622float2(hp);
    lp = __floats2bfloat162_rn(a - f.x, b - f.y);
}

// ---------------------------------------------------------------------------
// fp32 -> (bf16 hi, bf16 lo) split
// ---------------------------------------------------------------------------
__global__ void split_kernel(const float* __restrict__ in,
                             __nv_bfloat16* __restrict__ hi,
                             __nv_bfloat16* __restrict__ lo, int n) {
    int i = (blockIdx.x * blockDim.x + threadIdx.x) * 4;
    if (i >= n) return;
    float4 v = *(const float4*)(in + i);
    __nv_bfloat16 h[4], l[4];
    h[0] = __float2bfloat16(v.x); h[1] = __float2bfloat16(v.y);
    h[2] = __float2bfloat16(v.z); h[3] = __float2bfloat16(v.w);
    l[0] = __float2bfloat16(v.x - __bfloat162float(h[0]));
    l[1] = __float2bfloat16(v.y - __bfloat162float(h[1]));
    l[2] = __float2bfloat16(v.z - __bfloat162float(h[2]));
    l[3] = __float2bfloat16(v.w - __bfloat162float(h[3]));
    *(uint2*)(hi + i) = *(uint2*)h;
    *(uint2*)(lo + i) = *(uint2*)l;
}

// ---------------------------------------------------------------------------
// Warp-MMA split-bf16 GEMM (NT): C[M,N] = A[M,K] @ B[N,K]^T (fp32 result)
// occ 1 (evidence: occ-2 variant regressed 597->781us). One sync per chunk.
// ---------------------------------------------------------------------------
#define GEMM_LDA 40
#define GEMM_TILE_B (128 * GEMM_LDA * 2)     // 10240 B per tile
#define GEMM_STAGE_B (4 * GEMM_TILE_B)
#define GEMM_SMEM_B (2 * GEMM_STAGE_B)       // 81920 B

__global__ __launch_bounds__(256, 1)
void mma_gemm(const __nv_bfloat16* __restrict__ Ah, const __nv_bfloat16* __restrict__ Al,
              const __nv_bfloat16* __restrict__ Bh, const __nv_bfloat16* __restrict__ Bl,
              float* __restrict__ C, int M, int N, int K) {
    extern __shared__ __align__(1024) char dsm[];
    const uint32_t sb0 = smem_u32(dsm);

    const int tid = threadIdx.x;
    const int wid = tid >> 5;
    const int lane = tid & 31;
    const int bm = blockIdx.y * 128;
    const int bn = blockIdx.x * 128;

    const int wm = (wid & 1) * 64;
    const int wn = (wid >> 1) * 32;

    const int r_ld = tid >> 1;
    const int u0 = (tid & 1) * 2;

    auto load_chunk = [&](int c, int buf) {
        uint32_t s = sb0 + buf * GEMM_STAGE_B;
        const __nv_bfloat16* gA = Ah + (size_t)(bm + r_ld) * K + c * 32;
        const __nv_bfloat16* gAl = Al + (size_t)(bm + r_ld) * K + c * 32;
        const __nv_bfloat16* gB = Bh + (size_t)(bn + r_ld) * K + c * 32;
        const __nv_bfloat16* gBl = Bl + (size_t)(bn + r_ld) * K + c * 32;
        uint32_t so = (uint32_t)(r_ld * 80 + u0 * 16);
#pragma unroll
        for (int t = 0; t < 2; t++) {
            uint32_t o = so + t * 16;
            int e = (u0 + t) * 8;
            cp_async16(s + 0 * GEMM_TILE_B + o, gA + e);
            cp_async16(s + 1 * GEMM_TILE_B + o, gAl + e);
            cp_async16(s + 2 * GEMM_TILE_B + o, gB + e);
            cp_async16(s + 3 * GEMM_TILE_B + o, gBl + e);
        }
    };

    float acc[4][4][4];
#pragma unroll
    for (int i = 0; i < 4; i++)
#pragma unroll
        for (int j = 0; j < 4; j++)
#pragma unroll
            for (int e = 0; e < 4; e++) acc[i][j][e] = 0.f;

    const int nk = K >> 5;
    load_chunk(0, 0);
    CP_COMMIT();

    const int a_row = (lane & 15);
    const int a_koff = (lane >> 4) * 8;
    const int b_nrow = (lane & 7) + ((lane >> 4) << 3);
    const int b_koff = ((lane >> 3) & 1) * 8;

    for (int c = 0; c < nk; c++) {
        const int buf = c & 1;
        CP_WAIT0();
        __syncthreads();   // loads(c) visible AND all warps done computing c-1
        if (c + 1 < nk) { load_chunk(c + 1, buf ^ 1); CP_COMMIT(); }

        const uint32_t s = sb0 + buf * GEMM_STAGE_B;
        const uint32_t sAh = s;
        const uint32_t sAl = s + GEMM_TILE_B;
        const uint32_t sBh = s + 2 * GEMM_TILE_B;
        const uint32_t sBl = s + 3 * GEMM_TILE_B;

#pragma unroll
        for (int ks = 0; ks < 2; ks++) {
            const int kb = ks * 16;
            uint32_t ah[4][4], al[4][4], bh[2][4], bl[2][4];
#pragma unroll
            for (int mf = 0; mf < 4; mf++) {
                uint32_t off = (uint32_t)((wm + mf * 16 + a_row) * 80 +
                                          (kb + a_koff) * 2);
                ldsm4(ah[mf], sAh + off);
                ldsm4(al[mf], sAl + off);
            }
#pragma unroll
            for (int nf = 0; nf < 2; nf++) {
                uint32_t off = (uint32_t)((wn + nf * 16 + b_nrow) * 80 +
                                          (kb + b_koff) * 2);
                ldsm4(bh[nf], sBh + off);
                ldsm4(bl[nf], sBl + off);
            }
#pragma unroll
            for (int mf = 0; mf < 4; mf++)
#pragma unroll
                for (int n = 0; n < 4; n++) {
                    const int f2 = n >> 1, j = (n & 1) * 2;
                    mma_bf16(acc[mf][n], ah[mf], bh[f2][j], bh[f2][j + 1]);
                    mma_bf16(acc[mf][n], ah[mf], bl[f2][j], bl[f2][j + 1]);
                    mma_bf16(acc[mf][n], al[mf], bh[f2][j], bh[f2][j + 1]);
                }
        }
    }

    const int g = lane >> 2, tig = lane & 3;
#pragma unroll
    for (int mf = 0; mf < 4; mf++) {
#pragma unroll
        for (int n = 0; n < 4; n++) {
            int row0 = bm + wm + mf * 16 + g;
            int col = bn + wn + n * 8 + tig * 2;
            *(float2*)(C + (size_t)row0 * N + col) =
                make_float2(acc[mf][n][0], acc[mf][n][1]);
            *(float2*)(C + (size_t)(row0 + 8) * N + col) =
                make_float2(acc[mf][n][2], acc[mf][n][3]);
        }
    }
}

// ---------------------------------------------------------------------------
// Prep: RoPE(q)*scale -> Qh/Ql; RoPE(k_cur) -> Kh/Kl[.., XL+t];
//       k_xl+pos -> Kh/Kl[.., t]; v -> Vh/Vl.
// ---------------------------------------------------------------------------
__global__ void prep_kernel(const float* __restrict__ k_xl,
                            const float* __restrict__ v_xl,
                            const float* __restrict__ pos_emb,
                            const float* __restrict__ cosb,
                            const float* __restrict__ sinb) {
    int idx = blockIdx.x * blockDim.x + threadIdx.x;
    int i = idx & 63;
    int h = (idx >> 6) & (N_HEADS - 1);
    int t = (idx >> 10) & (SEQ_T - 1);
    int b = idx >> 20;
    if (b >= BATCH) return;

    const float scale = 0.08838834764831845f;
    int m = b * SEQ_T + t;
    float c = cosb[t * 64 + i];
    float s = sinb[t * 64 + i];
    int d0 = 2 * i;

    const float* qk_row = g_qkv + (size_t)m * (3 * D_MODEL);
    __nv_bfloat162 hp, lp;

    {
        float2 xv = *(const float2*)(qk_row + h * HEAD_DIM + d0);
        float o0 = (xv.x * c - xv.y * s) * scale;
        float o1 = (xv.x * s + xv.y * c) * scale;
        size_t base = ((size_t)(b * N_HEADS + h) * SEQ_T + t) * HEAD_DIM + d0;
        split2(o0, o1, hp, lp);
        *(__nv_bfloat162*)(g_Qh + base) = hp;
        *(__nv_bfloat162*)(g_Ql + base) = lp;
    }
    {
        float2 xv = *(const float2*)(qk_row + D_MODEL + h * HEAD_DIM + d0);
        float o0 = xv.x * c - xv.y * s;
        float o1 = xv.x * s + xv.y * c;
        size_t base = ((size_t)(b * N_HEADS + h) * KV_LEN + XL_LEN + t) * HEAD_DIM + d0;
        split2(o0, o1, hp, lp);
        *(__nv_bfloat162*)(g_Kh + base) = hp;
        *(__nv_bfloat162*)(g_Kl + base) = lp;
    }
    {
        float2 xv = *(const float2*)(qk_row + 2 * D_MODEL + h * HEAD_DIM + d0);
        size_t base = ((size_t)(b * N_HEADS + h) * KV_LEN + XL_LEN + t) * HEAD_DIM + d0;
        split2(xv.x, xv.y, hp, lp);
        *(__nv_bfloat162*)(g_Vh + base) = hp;
        *(__nv_bfloat162*)(g_Vl + base) = lp;
    }
    {
        int src = (b * XL_LEN + t) * D_MODEL + h * HEAD_DIM + d0;
        int psrc = t * D_MODEL + h * HEAD_DIM + d0;
        float2 kv = *(const float2*)(k_xl + src);
        float2 pv = *(const float2*)(pos_emb + psrc);
        float2 vv = *(const float2*)(v_xl + src);
        size_t base = ((size_t)(b * N_HEADS + h) * KV_LEN + t) * HEAD_DIM + d0;
        split2(kv.x + pv.x, kv.y + pv.y, hp, lp);
        *(__nv_bfloat162*)(g_Kh + base) = hp;
        *(__nv_bfloat162*)(g_Kl + base) = lp;
        split2(vv.x, vv.y, hp, lp);
        *(__nv_bfloat162*)(g_Vh + base) = hp;
        *(__nv_bfloat162*)(g_Vl + base) = lp;
    }
}

// ---------------------------------------------------------------------------
// Flash attention (mma.sync, split bf16). 128-row Q tile, 8 warps.
// KV chunk = 32 rows, single-buffered with split K/V prefetch
// (K(c+1) issued during PV(c), V(c+1) during QK(c+1)). 2 CTAs/SM.
// ---------------------------------------------------------------------------
#define ALD 272                     // smem row stride bytes
#define AQT_B (128 * ALD)           // Q tile (34816 B) x2 (hi/lo)
#define AKV_B (32 * ALD)            // 8704 B per KV tensor
#define ATT_SMEM_B (2 * AQT_B + 4 * AKV_B)   // 104448 B -> 2 CTAs/SM
#define NCHUNK (KV_LEN / 32)        // 64

__global__ __launch_bounds__(256, 2)
void attn_mma(const int* __restrict__ iscp) {
    extern __shared__ __align__(256) char smb[];
    const int tid = threadIdx.x;
    const int wid = tid >> 5;
    const int lane = tid & 31;
    const int q0 = blockIdx.x * 128;
    const int h = blockIdx.y;
    const int b = blockIdx.z;
    const bool causal = (*iscp) != 0;
    const int diag = KV_LEN - SEQ_T;

    const uint32_t sb = smem_u32(smb);
    const uint32_t qh_b = sb;                    // Qh
    const uint32_t kh_b = sb + 2 * AQT_B;        // Kh
    const uint32_t vh_b = kh_b + 2 * AKV_B;      // Vh

    const __nv_bfloat16* Qhg = g_Qh + ((size_t)(b * N_HEADS + h) * SEQ_T + q0) * HEAD_DIM;
    const __nv_bfloat16* Qlg = g_Ql + ((size_t)(b * N_HEADS + h) * SEQ_T + q0) * HEAD_DIM;
    const __nv_bfloat16* Khg = g_Kh + (size_t)(b * N_HEADS + h) * KV_LEN * HEAD_DIM;
    const __nv_bfloat16* Klg = g_Kl + (size_t)(b * N_HEADS + h) * KV_LEN * HEAD_DIM;
    const __nv_bfloat16* Vhg = g_Vh + (size_t)(b * N_HEADS + h) * KV_LEN * HEAD_DIM;
    const __nv_bfloat16* Vlg = g_Vl + (size_t)(b * N_HEADS + h) * KV_LEN * HEAD_DIM;

    // KV loaders: 32 rows x 256 B per tensor; 4 cp.async16 per thread per pair
    const int kv_r = tid >> 3;               // row 0..31
    const int kv_u = (tid & 7) * 2;          // unit 0..14 step 2
    auto load_K = [&](int c) {
        const char* gh = (const char*)(Khg + (size_t)c * 32 * HEAD_DIM);
        const char* gl = (const char*)(Klg + (size_t)c * 32 * HEAD_DIM);
#pragma unroll
        for (int u = 0; u < 2; u++) {
            uint32_t so = (uint32_t)(kv_r * ALD + (kv_u + u) * 16);
            uint32_t go = (uint32_t)(kv_r * 256 + (kv_u + u) * 16);
            cp_async16(kh_b + so, gh + go);
            cp_async16(kh_b + AKV_B + so, gl + go);
        }
        CP_COMMIT();
    };
    auto load_V = [&](int c) {
        const char* gh = (const char*)(Vhg + (size_t)c * 32 * HEAD_DIM);
        const char* gl = (const char*)(Vlg + (size_t)c * 32 * HEAD_DIM);
#pragma unroll
        for (int u = 0; u < 2; u++) {
            uint32_t so = (uint32_t)(kv_r * ALD + (kv_u + u) * 16);
            uint32_t go = (uint32_t)(kv_r * 256 + (kv_u + u) * 16);
            cp_async16(vh_b + so, gh + go);
            cp_async16(vh_b + AKV_B + so, gl + go);
        }
        CP_COMMIT();
    };

    // Q tile loads (no commit: folded into first K group)
#pragma unroll
    for (int u = 0; u < 8; u++) {
        int idx = tid * 8 + u;
        int r = idx >> 4, un = idx & 15;
        uint32_t so = (uint32_t)(r * ALD + un * 16);
        cp_async16(qh_b + so, (const char*)Qhg + r * 256 + un * 16);
        cp_async16(qh_b + AQT_B + so, (const char*)Qlg + r * 256 + un * 16);
    }
    load_K(0);   // commits Q + K0 as one group
    load_V(0);

    float m_lo = -1e30f, m_hi = -1e30f, l_lo = 0.f, l_hi = 0.f;
    float O[16][4];
#pragma unroll
    for (int t = 0; t < 16; t++)
#pragma unroll
        for (int e = 0; e < 4; e++) O[t][e] = 0.f;

    const int a_row = lane & 15;
    const int a_koff = (lane >> 4) * 8;
    const int b_nrow = (lane & 7) + ((lane >> 4) << 3);
    const int b_koff = ((lane >> 3) & 1) * 8;

    for (int c = 0; c < NCHUNK; c++) {
        // ---- wait K(c) (V(c) may still be in flight) ----
        CP_WAIT1();
        __syncthreads();

        // ---- S = Q K^T over 32 kv cols ----
        float s[4][4];
#pragma unroll
        for (int t = 0; t < 4; t++)
#pragma unroll
            for (int e = 0; e < 4; e++) s[t][e] = 0.f;

#pragma unroll
        for (int ks = 0; ks < 8; ks++) {
            uint32_t qa = qh_b + (uint32_t)((wid * 16 + a_row) * ALD +
                                            (ks * 16 + a_koff) * 2);
            uint32_t qh[4], ql[4];
            ldsm4(qh, qa);
            ldsm4(ql, qa + AQT_B);
            uint32_t kcol = (uint32_t)((ks * 16 + b_koff) * 2);
#pragma unroll
            for (int ng = 0; ng < 2; ng++) {
                uint32_t ka = kh_b + (uint32_t)((ng * 16 + b_nrow) * ALD) + kcol;
                uint32_t kh4[4], kl4[4];
                ldsm4(kh4, ka);
                ldsm4(kl4, ka + AKV_B);
#pragma unroll
                for (int half = 0; half < 2; half++) {
                    int t = ng * 2 + half;
                    int j = half * 2;
                    mma_bf16(s[t], qh, kh4[j], kh4[j + 1]);
                    mma_bf16(s[t], qh, kl4[j], kl4[j + 1]);
                    mma_bf16(s[t], ql, kh4[j], kh4[j + 1]);
                }
            }
        }
        __syncthreads();            // all warps done reading K region
        if (c + 1 < NCHUNK) load_K(c + 1);

        // ---- mask + online softmax ----
        if (causal) {
            int row_lo = q0 + wid * 16 + (lane >> 2);
#pragma unroll
            for (int t = 0; t < 4; t++) {
                int col = c * 32 + t * 8 + (lane & 3) * 2;
                if (col > row_lo + diag)         s[t][0] = -1e30f;
                if (col + 1 > row_lo + diag)     s[t][1] = -1e30f;
                if (col > row_lo + 8 + diag)     s[t][2] = -1e30f;
                if (col + 1 > row_lo + 8 + diag) s[t][3] = -1e30f;
            }
        }

        float mx_lo = -1e30f, mx_hi = -1e30f;
#pragma unroll
        for (int t = 0; t < 4; t++) {
            mx_lo = fmaxf(mx_lo, fmaxf(s[t][0], s[t][1]));
            mx_hi = fmaxf(mx_hi, fmaxf(s[t][2], s[t][3]));
        }
        mx_lo = fmaxf(mx_lo, __shfl_xor_sync(0xffffffffu, mx_lo, 1));
        mx_lo = fmaxf(mx_lo, __shfl_xor_sync(0xffffffffu, mx_lo, 2));
        mx_hi = fmaxf(mx_hi, __shfl_xor_sync(0xffffffffu, mx_hi, 1));
        mx_hi = fmaxf(mx_hi, __shfl_xor_sync(0xffffffffu, mx_hi, 2));

        float mn_lo = fmaxf(m_lo, mx_lo);
        float mn_hi = fmaxf(m_hi, mx_hi);
        float cf_lo = __expf(m_lo - mn_lo);
        float cf_hi = __expf(m_hi - mn_hi);
        m_lo = mn_lo; m_hi = mn_hi;

        float sum_lo = 0.f, sum_hi = 0.f;
#pragma unroll
        for (int t = 0; t < 4; t++) {
            s[t][0] = __expf(s[t][0] - mn_lo); sum_lo += s[t][0];
            s[t][1] = __expf(s[t][1] - mn_lo); sum_lo += s[t][1];
            s[t][2] = __expf(s[t][2] - mn_hi); sum_hi += s[t][2];
            s[t][3] = __expf(s[t][3] - mn_hi); sum_hi += s[t][3];
        }
        sum_lo += __shfl_xor_sync(0xffffffffu, sum_lo, 1);
        sum_lo += __shfl_xor_sync(0xffffffffu, sum_lo, 2);
        sum_hi += __shfl_xor_sync(0xffffffffu, sum_hi, 1);
        sum_hi += __shfl_xor_sync(0xffffffffu, sum_hi, 2);
        l_lo = l_lo * cf_lo + sum_lo;
        l_hi = l_hi * cf_hi + sum_hi;

#pragma unroll
        for (int t = 0; t < 16; t++) {
            O[t][0] *= cf_lo; O[t][1] *= cf_lo;
            O[t][2] *= cf_hi; O[t][3] *= cf_hi;
        }

        // ---- pack P fragments ----
        uint32_t ph[2][4], pl[2][4];
#pragma unroll
        for (int j = 0; j < 2; j++) {
            float ra, rb;
            ph[j][0] = pack_hi(s[2 * j][0], s[2 * j][1], ra, rb);
            pl[j][0] = pack2(ra, rb);
            ph[j][1] = pack_hi(s[2 * j][2], s[2 * j][3], ra, rb);
            pl[j][1] = pack2(ra, rb);
            ph[j][2] = pack_hi(s[2 * j + 1][0], s[2 * j + 1][1], ra, rb);
            pl[j][2] = pack2(ra, rb);
            ph[j][3] = pack_hi(s[2 * j + 1][2], s[2 * j + 1][3], ra, rb);
            pl[j][3] = pack2(ra, rb);
        }

        // ---- wait V(c) (K(c+1) may still be in flight) ----
        if (c + 1 < NCHUNK) { CP_WAIT1(); } else { CP_WAIT0(); }
        __syncthreads();

        // ---- O += P V ----
#pragma unroll
        for (int j = 0; j < 2; j++) {
            uint32_t vrow = (uint32_t)((j * 16 + a_row) * ALD);
#pragma unroll
            for (int dg = 0; dg < 8; dg++) {
                uint32_t va = vh_b + vrow + (uint32_t)((dg * 16 + a_koff) * 2);
                uint32_t vh4[4], vl4[4];
                ldsm4t(vh4, va);
                ldsm4t(vl4, va + AKV_B);
                int t0 = dg * 2, t1 = t0 + 1;
                mma_bf16(O[t0], ph[j], vh4[0], vh4[1]);
                mma_bf16(O[t1], ph[j], vh4[2], vh4[3]);
                mma_bf16(O[t0], ph[j], vl4[0], vl4[1]);
                mma_bf16(O[t1], ph[j], vl4[2], vl4[3]);
                mma_bf16(O[t0], pl[j], vh4[0], vh4[1]);
                mma_bf16(O[t1], pl[j], vh4[2], vh4[3]);
            }
        }
        __syncthreads();            // all warps done reading V region
        if (c + 1 < NCHUNK) load_V(c + 1);
    }

    // ---- epilogue: y = O / l, bf16 hi/lo for proj GEMM ----
    float inv_lo = 1.f / l_lo, inv_hi = 1.f / l_hi;
    int row_lo = q0 + wid * 16 + (lane >> 2);
    int row_hi = row_lo + 8;
#pragma unroll
    for (int t = 0; t < 16; t++) {
        int col = h * HEAD_DIM + t * 8 + (lane & 3) * 2;
        __nv_bfloat162 hp, lp;
        size_t o0 = (size_t)(b * SEQ_T + row_lo) * D_MODEL + col;
        split2(O[t][0] * inv_lo, O[t][1] * inv_lo, hp, lp);
        *(__nv_bfloat162*)(g_yh + o0) = hp;
        *(__nv_bfloat162*)(g_yl + o0) = lp;
        size_t o1 = (size_t)(b * SEQ_T + row_hi) * D_MODEL + col;
        split2(O[t][2] * inv_hi, O[t][3] * inv_hi, hp, lp);
        *(__nv_bfloat162*)(g_yh + o1) = hp;
        *(__nv_bfloat162*)(g_yl + o1) = lp;
    }
}

// ---------------------------------------------------------------------------
extern "C" void kernel_launch(void* const* d_in, const int* in_sizes, int n_in,
                              void* d_out, int out_size) {
    const float* x       = (const float*)d_in[0];
    const float* cosb    = (const float*)d_in[1];
    const float* sinb    = (const float*)d_in[2];
    const float* k_xl    = (const float*)d_in[3];
    const float* v_xl    = (const float*)d_in[4];
    const float* pos_emb = (const float*)d_in[5];
    const float* w_qkv   = (const float*)d_in[6];
    const float* w_proj  = (const float*)d_in[7];
    const int*   iscp    = (const int*)d_in[8];
    float* out = (float*)d_out;

    float* qkv_p;
    __nv_bfloat16 *xh, *xl, *wqh, *wql, *wph, *wpl, *yh, *yl;
    cudaGetSymbolAddress((void**)&qkv_p, g_qkv);
    cudaGetSymbolAddress((void**)&xh, g_xh);
    cudaGetSymbolAddress((void**)&xl, g_xl);
    cudaGetSymbolAddress((void**)&wqh, g_wqh);
    cudaGetSymbolAddress((void**)&wql, g_wql);
    cudaGetSymbolAddress((void**)&wph, g_wph);
    cudaGetSymbolAddress((void**)&wpl, g_wpl);
    cudaGetSymbolAddress((void**)&yh, g_yh);
    cudaGetSymbolAddress((void**)&yl, g_yl);

    cudaFuncSetAttribute(mma_gemm,
                         cudaFuncAttributeMaxDynamicSharedMemorySize, GEMM_SMEM_B);
    cudaFuncSetAttribute(attn_mma,
                         cudaFuncAttributeMaxDynamicSharedMemorySize, ATT_SMEM_B);

    // 0) split x / w_qkv / w_proj into bf16 hi+lo
    {
        int nx = M_ROWS * D_MODEL;
        int nwq = 3 * D_MODEL * D_MODEL;
        int nwp = D_MODEL * D_MODEL;
        split_kernel<<<nx / 1024, 256>>>(x, xh, xl, nx);
        split_kernel<<<nwq / 1024, 256>>>(w_qkv, wqh, wql, nwq);
        split_kernel<<<nwp / 1024, 256>>>(w_proj, wph, wpl, nwp);
    }

    // 1) qkv = x @ w_qkv^T
    mma_gemm<<<dim3(3 * D_MODEL / 128, M_ROWS / 128), 256, GEMM_SMEM_B>>>(
        xh, xl, wqh, wql, qkv_p, M_ROWS, 3 * D_MODEL, D_MODEL);

    // 2) rope / concat / split into bf16
    {
        int total = BATCH * SEQ_T * N_HEADS * (HEAD_DIM / 2);
        prep_kernel<<<total / 256, 256>>>(k_xl, v_xl, pos_emb, cosb, sinb);
    }

    // 3) attention (tensor-core flash, split bf16, 2 CTAs/SM)
    attn_mma<<<dim3(SEQ_T / 128, N_HEADS, BATCH), 256, ATT_SMEM_B>>>(iscp);

    // 4) out = y @ w_proj^T
    mma_gemm<<<dim3(D_MODEL / 128, M_ROWS / 128), 256, GEMM_SMEM_B>>>(
        yh, yl, wph, wpl, out, M_ROWS, D_MODEL, D_MODEL);
}